// round 1
// baseline (speedup 1.0000x reference)
#include <cuda_runtime.h>
#include <math.h>
#include <stdint.h>

#define cB 8
#define cN 128
#define cF 128
#define cTf 64
#define cTm 256
#define cDf 32
#define cDm 128
#define cE 64
#define cH 128
#define cTE 64

// ---------------- device scratch (no allocations allowed) ----------------
__device__ float g_kvT[cB*cH*cTm];   // [b][h][m]
__device__ float g_cond[cB*cN*cH];   // cond_t
__device__ float g_h[cB*cN*cE];
__device__ float g_TEW[cB*cH];       // time_emb @ W1_time + b1
__device__ float g_A[cB*cN*cH];      // i-side
__device__ float g_Bv[cB*cN*cH];     // j-side (hj + cond + time + b1)

// ---------------- packed f32x2 helpers ----------------
__device__ __forceinline__ unsigned long long pack2(float x){
    unsigned long long r;
    asm("mov.b64 %0, {%1, %1};" : "=l"(r) : "f"(x));
    return r;
}
__device__ __forceinline__ void fma2(unsigned long long &acc, unsigned long long a, unsigned long long b){
    asm("fma.rn.f32x2 %0, %1, %2, %0;" : "+l"(acc) : "l"(a), "l"(b));
}
__device__ __forceinline__ float2 ull2f2(unsigned long long v){
    float2 f;
    asm("mov.b64 {%0, %1}, %2;" : "=f"(f.x), "=f"(f.y) : "l"(v));
    return f;
}

// ---------------- kv = feat_music @ music_W + music_b, stored transposed ----------------
__global__ void __launch_bounds__(256) kv_kernel(const float* __restrict__ music,
                                                 const float* __restrict__ W,
                                                 const float* __restrict__ bias){
    extern __shared__ float sm[];            // musT [d=128][m=256] pitch 257
    int b  = blockIdx.y;
    int hc = blockIdx.x;                     // 8 chunks of 16 h
    int tid = threadIdx.x;
    for (int idx = tid; idx < cTm*cDm; idx += 256){
        int m = idx >> 7, d = idx & 127;
        sm[d*257 + m] = music[((size_t)b*cTm + m)*cDm + d];
    }
    __syncthreads();
    int m = tid;                              // 256 threads = 256 m
    for (int hh = 0; hh < 16; hh++){
        int h = hc*16 + hh;
        float acc = bias[h];
        #pragma unroll 8
        for (int d = 0; d < cDm; d++)
            acc = fmaf(sm[d*257 + m], W[d*cH + h], acc);
        g_kvT[((size_t)b*cH + h)*cTm + m] = acc;
    }
}

// ---------------- h = node_feats @ node_W + node_b ----------------
__global__ void __launch_bounds__(64) h_kernel(const float* __restrict__ nf,
                                               const float* __restrict__ Wn,
                                               const float* __restrict__ bn){
    __shared__ float row[cF];
    int bid = blockIdx.x, tid = threadIdx.x;
    row[tid]      = nf[(size_t)bid*cF + tid];
    row[tid + 64] = nf[(size_t)bid*cF + tid + 64];
    __syncthreads();
    float acc = bn[tid];
    #pragma unroll 8
    for (int f = 0; f < cF; f++) acc = fmaf(row[f], Wn[f*cE + tid], acc);
    g_h[(size_t)bid*cE + tid] = acc;
}

// ---------------- TEW[b,k] = time_emb(t[b]) @ W1_time + b1 ----------------
__global__ void __launch_bounds__(128) te_kernel(const int* __restrict__ t,
                                                 const float* __restrict__ W1,
                                                 const float* __restrict__ b1){
    __shared__ float te[cTE];
    int b = blockIdx.x, tid = threadIdx.x;
    if (tid < 32){
        int ti = t[b]; ti = ti < 0 ? 0 : (ti > cTf-1 ? cTf-1 : ti);
        float invf = expf(-(float)tid * (logf(10000.0f) / 31.0f));
        float fr = (float)ti * invf;
        te[tid]      = sinf(fr);
        te[tid + 32] = cosf(fr);
    }
    __syncthreads();
    float acc = b1[tid];
    #pragma unroll
    for (int e = 0; e < cTE; e++) acc = fmaf(te[e], W1[(2*cE + 2 + cH + e)*cH + tid], acc);
    g_TEW[b*cH + tid] = acc;
}

// ---------------- attention: q, scores, softmax, entropy, attn_weights, ctx@t ----------------
__global__ void __launch_bounds__(256, 1) attn_kernel(const float* __restrict__ feat_fnirs,
                                                      const float* __restrict__ fnirs_W,
                                                      const float* __restrict__ fnirs_b,
                                                      const int* __restrict__ t,
                                                      float* __restrict__ out_attn,
                                                      float* __restrict__ out_loss){
    extern __shared__ float sm[];
    float* kvT = sm;               // [h=128][m=256]   32768 f
    float* qT  = sm + 32768;       // [h=128][f=64]     8192 f
    float* S   = sm + 40960;       // scores [f=64][m=256] 16384 f (reused for feat/W staging)
    float* red = sm + 57344;       // 8 f
    int tid = threadIdx.x;
    int bid = blockIdx.x;
    int b   = bid >> 7;

    // stage kvT (straight copy, coalesced)
    {
        const float4* src = (const float4*)(g_kvT + (size_t)b*cH*cTm);
        float4* dst = (float4*)kvT;
        #pragma unroll
        for (int i = 0; i < 32; i++) dst[tid + i*256] = src[tid + i*256];
    }
    // stage fnirs tile + weights into S region
    {
        const float4* fsrc = (const float4*)(feat_fnirs + (size_t)bid*cTf*cDf);
        float4* fdst = (float4*)S;                 // 512 f4
        for (int i = tid; i < 512; i += 256) fdst[i] = fsrc[i];
        const float4* wsrc = (const float4*)fnirs_W;
        float4* wdst = (float4*)(S + 2048);        // 1024 f4
        for (int i = tid; i < 1024; i += 256) wdst[i] = wsrc[i];
    }
    __syncthreads();

    // q^T[h][f] = fnirs_b[h] + feat[f,:] . fnirs_W[:,h]
    {
        int h = tid & 127, fh = tid >> 7;
        const float* Wf = S + 2048;
        float w[32];
        #pragma unroll
        for (int d = 0; d < 32; d++) w[d] = Wf[d*cH + h];
        float bias = fnirs_b[h];
        for (int f = fh*32; f < fh*32 + 32; f++){
            const float4* fr = (const float4*)(S + f*cDf);
            float acc = bias;
            #pragma unroll
            for (int d4 = 0; d4 < 8; d4++){
                float4 v = fr[d4];
                acc = fmaf(v.x, w[d4*4+0], acc);
                acc = fmaf(v.y, w[d4*4+1], acc);
                acc = fmaf(v.z, w[d4*4+2], acc);
                acc = fmaf(v.w, w[d4*4+3], acc);
            }
            qT[h*cTf + f] = acc;
        }
    }
    __syncthreads();

    // scores = scale * q @ kv^T : 128 active threads, 8f x 16m register tile, f32x2 packed FMA
    if (tid < 128){
        int tm = tid & 15, tf = tid >> 4;
        int m0 = tm*16, f0 = tf*8;
        unsigned long long acc[8][8];
        #pragma unroll
        for (int fi = 0; fi < 8; fi++)
            #pragma unroll
            for (int p = 0; p < 8; p++) acc[fi][p] = 0ull;
        for (int h = 0; h < cH; h++){
            const float* qp = qT + h*cTf + f0;
            float4 qa = *(const float4*)qp;
            float4 qb = *(const float4*)(qp + 4);
            unsigned long long qq[8] = {pack2(qa.x), pack2(qa.y), pack2(qa.z), pack2(qa.w),
                                        pack2(qb.x), pack2(qb.y), pack2(qb.z), pack2(qb.w)};
            const ulonglong2* kp = (const ulonglong2*)(kvT + h*cTm + m0);
            ulonglong2 k0 = kp[0], k1 = kp[1], k2 = kp[2], k3 = kp[3];
            unsigned long long kk[8] = {k0.x, k0.y, k1.x, k1.y, k2.x, k2.y, k3.x, k3.y};
            #pragma unroll
            for (int fi = 0; fi < 8; fi++)
                #pragma unroll
                for (int p = 0; p < 8; p++)
                    fma2(acc[fi][p], qq[fi], kk[p]);
        }
        const float scale = 0.0883883476483184f;   // 1/sqrt(128)
        #pragma unroll
        for (int fi = 0; fi < 8; fi++){
            float* srow = S + (f0 + fi)*cTm + m0;
            #pragma unroll
            for (int p = 0; p < 8; p++){
                float2 v = ull2f2(acc[fi][p]);
                ((float2*)srow)[p] = make_float2(v.x*scale, v.y*scale);
            }
        }
    }
    __syncthreads();

    // softmax rows + entropy + attn_weights accumulation (8 rows / warp)
    int w = tid >> 5, lane = tid & 31;
    float entacc = 0.f;
    for (int r = 0; r < 8; r++){
        int f = w*8 + r;
        float* srow = S + f*cTm;
        float v[8];
        float mx = -1e30f;
        #pragma unroll
        for (int k = 0; k < 8; k++){ v[k] = srow[lane + 32*k]; mx = fmaxf(mx, v[k]); }
        #pragma unroll
        for (int o = 16; o > 0; o >>= 1) mx = fmaxf(mx, __shfl_xor_sync(0xffffffffu, mx, o));
        float ssum = 0.f;
        #pragma unroll
        for (int k = 0; k < 8; k++){ v[k] = __expf(v[k] - mx); ssum += v[k]; }
        #pragma unroll
        for (int o = 16; o > 0; o >>= 1) ssum += __shfl_xor_sync(0xffffffffu, ssum, o);
        float inv = 1.f / ssum;
        float* arow = out_attn + ((size_t)b*cTf + f)*cTm;
        #pragma unroll
        for (int k = 0; k < 8; k++){
            float p = v[k]*inv;
            srow[lane + 32*k] = p;
            entacc -= p*__logf(p + 1e-8f);
            atomicAdd(&arow[lane + 32*k], p * (1.f/128.f));   // mean over N
        }
    }
    #pragma unroll
    for (int o = 16; o > 0; o >>= 1) entacc += __shfl_xor_sync(0xffffffffu, entacc, o);
    if (lane == 0) red[w] = entacc;
    __syncthreads();
    if (tid == 0){
        float tot = 0.f;
        #pragma unroll
        for (int i = 0; i < 8; i++) tot += red[i];
        atomicAdd(out_loss, tot * (1.f/(float)(cB*cN*cTf)));
    }

    // ctx only for the gathered time row; cond_t = q[t] + ctx
    int trow = t[b]; trow = trow < 0 ? 0 : (trow > cTf-1 ? cTf-1 : trow);
    const float* prow = S + trow*cTm;
    for (int hi = 0; hi < 16; hi++){
        int h = w*16 + hi;
        const float* krow = kvT + h*cTm;
        float acc = 0.f;
        #pragma unroll
        for (int mm = 0; mm < 8; mm++)
            acc = fmaf(prow[lane + 32*mm], krow[lane + 32*mm], acc);
        #pragma unroll
        for (int o = 16; o > 0; o >>= 1) acc += __shfl_xor_sync(0xffffffffu, acc, o);
        if (lane == 0) g_cond[(size_t)bid*cH + h] = qT[h*cTf + trow] + acc;
    }
}

// ---------------- A = h@W1_hi ; Bv = h@W1_hj + cond@W1_cond + TEW ----------------
__global__ void __launch_bounds__(128) ab_kernel(const float* __restrict__ W1){
    __shared__ float hrow[cE];
    __shared__ float crow[cH];
    int bid = blockIdx.x, tid = threadIdx.x;
    if (tid < cE) hrow[tid] = g_h[(size_t)bid*cE + tid];
    crow[tid] = g_cond[(size_t)bid*cH + tid];
    __syncthreads();
    int b = bid >> 7;
    float a = 0.f, bv = g_TEW[b*cH + tid];
    #pragma unroll 8
    for (int e = 0; e < cE; e++) a = fmaf(hrow[e], W1[e*cH + tid], a);
    #pragma unroll 8
    for (int e = 0; e < cE; e++) bv = fmaf(hrow[e], W1[(cE + e)*cH + tid], bv);
    #pragma unroll 8
    for (int c = 0; c < cH; c++) bv = fmaf(crow[c], W1[(2*cE + 2 + c)*cH + tid], bv);
    g_A[(size_t)bid*cH + tid]  = a;
    g_Bv[(size_t)bid*cH + tid] = bv;
}

// ---------------- noise_pred[b,i,j] = relu(A_i + Bv_j + adj*wa + gpre*wg) @ W2 + b2 ----------------
__global__ void __launch_bounds__(128) final_kernel(const float* __restrict__ adj,
                                                    const float* __restrict__ gpre,
                                                    const float* __restrict__ W1,
                                                    const float* __restrict__ W2,
                                                    const float* __restrict__ b2,
                                                    float* __restrict__ out){
    extern __shared__ float sm[];
    float*  BvS = sm;                         // [j=128][k=128] pitch 129 -> conflict free
    float*  A_s = sm + 128*129;               // 128
    float4* W3  = (float4*)(sm + 128*129 + 128);  // 128 x (wa, wg, w2, 0)
    int b = blockIdx.y, ic = blockIdx.x, tid = threadIdx.x;
    for (int r = 0; r < cN; r++)
        BvS[r*129 + tid] = g_Bv[((size_t)b*cN + r)*cH + tid];
    W3[tid] = make_float4(W1[(2*cE)*cH + tid], W1[(2*cE + 1)*cH + tid], W2[tid], 0.f);
    float b2v = b2[0];
    __syncthreads();
    for (int ii = 0; ii < 8; ii++){
        int i = ic*8 + ii;
        A_s[tid] = g_A[((size_t)b*cN + i)*cH + tid];
        __syncthreads();
        size_t rbase = ((size_t)b*cN + i)*cN + tid;
        float adjv = adj[rbase], gv = gpre[rbase];
        const float* brow = BvS + tid*129;
        float acc = 0.f;
        #pragma unroll 4
        for (int k = 0; k < cH; k++){
            float4 ww = W3[k];
            float pre = A_s[k] + brow[k] + adjv*ww.x + gv*ww.y;
            acc = fmaf(fmaxf(pre, 0.f), ww.z, acc);
        }
        out[rbase] = acc + b2v;
        __syncthreads();
    }
}

// ---------------- launch ----------------
extern "C" void kernel_launch(void* const* d_in, const int* in_sizes, int n_in,
                              void* d_out, int out_size){
    const float* noisy_adj  = (const float*)d_in[0];
    const float* node_feats = (const float*)d_in[1];
    const float* feat_fnirs = (const float*)d_in[2];
    const float* feat_music = (const float*)d_in[3];
    const float* g_pre      = (const float*)d_in[4];
    const float* node_W     = (const float*)d_in[5];
    const float* node_b     = (const float*)d_in[6];
    const float* fnirs_W    = (const float*)d_in[7];
    const float* fnirs_b    = (const float*)d_in[8];
    const float* music_W    = (const float*)d_in[9];
    const float* music_b    = (const float*)d_in[10];
    const float* mlp_W1     = (const float*)d_in[11];
    const float* mlp_b1     = (const float*)d_in[12];
    const float* mlp_W2     = (const float*)d_in[13];
    const float* mlp_b2     = (const float*)d_in[14];
    const int*   t          = (const int*)d_in[15];

    float* out      = (float*)d_out;
    float* out_attn = out + cB*cN*cN;                  // 131072
    float* out_loss = out + cB*cN*cN + cB*cTf*cTm;     // 262144

    cudaFuncSetAttribute(kv_kernel,    cudaFuncAttributeMaxDynamicSharedMemorySize, 131584);
    cudaFuncSetAttribute(attn_kernel,  cudaFuncAttributeMaxDynamicSharedMemorySize, 229440);
    cudaFuncSetAttribute(final_kernel, cudaFuncAttributeMaxDynamicSharedMemorySize, 68608);

    cudaMemsetAsync(out_attn, 0, (size_t)(cB*cTf*cTm + 1)*sizeof(float));

    kv_kernel<<<dim3(8, cB), 256, 131584>>>(feat_music, music_W, music_b);
    h_kernel<<<cB*cN, 64>>>(node_feats, node_W, node_b);
    te_kernel<<<cB, 128>>>(t, mlp_W1, mlp_b1);
    attn_kernel<<<cB*cN, 256, 229440>>>(feat_fnirs, fnirs_W, fnirs_b, t, out_attn, out_loss);
    ab_kernel<<<cB*cN, 128>>>(mlp_W1);
    final_kernel<<<dim3(16, cB), 128, 68608>>>(noisy_adj, g_pre, mlp_W1, mlp_W2, mlp_b2, out);
}

// round 2
// speedup vs baseline: 1.3894x; 1.3894x over previous
#include <cuda_runtime.h>
#include <math.h>

#define cB 8
#define cN 128
#define cF 128
#define cTf 64
#define cTm 256
#define cDf 32
#define cDm 128
#define cE 64
#define cH 128
#define cTE 64
#define NP 8

typedef unsigned long long ull;

// ---------------- device scratch ----------------
__device__ float g_kvT[cB*cH*cTm];        // [b][h][m]
__device__ float g_q[cB*cN*cTf*cH];       // [b][n][f][h]
__device__ float g_cond[cB*cN*cH];
__device__ float g_h[cB*cN*cE];
__device__ float g_TEW[cB*cH];
__device__ float g_A[cB*cN*cH];
__device__ float g_Bv[cB*cN*cH];

// ---------------- packed f32x2 helpers ----------------
__device__ __forceinline__ ull pack2(float x){
    ull r; asm("mov.b64 %0, {%1, %1};" : "=l"(r) : "f"(x)); return r;
}
__device__ __forceinline__ ull packab(float a, float b){
    ull r; asm("mov.b64 %0, {%1, %2};" : "=l"(r) : "f"(a), "f"(b)); return r;
}
__device__ __forceinline__ void fma2(ull &acc, ull a, ull b){
    asm("fma.rn.f32x2 %0, %1, %2, %0;" : "+l"(acc) : "l"(a), "l"(b));
}
__device__ __forceinline__ float2 ull2f2(ull v){
    float2 f; asm("mov.b64 {%0, %1}, %2;" : "=f"(f.x), "=f"(f.y) : "l"(v)); return f;
}

// ---------------- kv = feat_music @ music_W + music_b (transposed) ----------------
__global__ void __launch_bounds__(256) kv_kernel(const float* __restrict__ music,
                                                 const float* __restrict__ W,
                                                 const float* __restrict__ bias){
    extern __shared__ float sm[];            // musT [d=128][m=256] pitch 257
    int b  = blockIdx.y;
    int hc = blockIdx.x;
    int tid = threadIdx.x;
    for (int idx = tid; idx < cTm*cDm; idx += 256){
        int m = idx >> 7, d = idx & 127;
        sm[d*257 + m] = music[((size_t)b*cTm + m)*cDm + d];
    }
    __syncthreads();
    int m = tid;
    for (int hh = 0; hh < 16; hh++){
        int h = hc*16 + hh;
        float acc = bias[h];
        #pragma unroll 8
        for (int d = 0; d < cDm; d++)
            acc = fmaf(sm[d*257 + m], W[d*cH + h], acc);
        g_kvT[((size_t)b*cH + h)*cTm + m] = acc;
    }
}

// ---------------- q precompute: g_q[b][n][f][h] ----------------
__global__ void __launch_bounds__(128) qpre_kernel(const float* __restrict__ feat,
                                                   const float* __restrict__ W,
                                                   const float* __restrict__ bias){
    __shared__ float sfeat[cTf*cDf];          // 2048 floats
    int bn = blockIdx.x, tid = threadIdx.x;
    {
        const float4* fs = (const float4*)(feat + (size_t)bn*cTf*cDf);
        float4* fd = (float4*)sfeat;
        #pragma unroll
        for (int i = tid; i < 512; i += 128) fd[i] = fs[i];
    }
    float w[cDf];
    #pragma unroll
    for (int d = 0; d < cDf; d++) w[d] = W[d*cH + tid];
    float bs = bias[tid];
    __syncthreads();
    float* qbase = g_q + (size_t)bn*cTf*cH;
    for (int j = 0; j < 32; j++){
        ull acc = pack2(bs);
        const float* ra = sfeat + (2*j)*cDf;
        const float* rb = sfeat + (2*j+1)*cDf;
        #pragma unroll
        for (int d = 0; d < cDf; d++)
            fma2(acc, packab(ra[d], rb[d]), pack2(w[d]));
        float2 q2 = ull2f2(acc);
        qbase[(2*j)*cH + tid]   = q2.x;
        qbase[(2*j+1)*cH + tid] = q2.y;
    }
}

// ---------------- h = node_feats @ node_W + node_b ----------------
__global__ void __launch_bounds__(64) h_kernel(const float* __restrict__ nf,
                                               const float* __restrict__ Wn,
                                               const float* __restrict__ bn){
    __shared__ float row[cF];
    int bid = blockIdx.x, tid = threadIdx.x;
    row[tid]      = nf[(size_t)bid*cF + tid];
    row[tid + 64] = nf[(size_t)bid*cF + tid + 64];
    __syncthreads();
    float acc = bn[tid];
    #pragma unroll 8
    for (int f = 0; f < cF; f++) acc = fmaf(row[f], Wn[f*cE + tid], acc);
    g_h[(size_t)bid*cE + tid] = acc;
}

// ---------------- TEW[b,k] = time_emb(t[b]) @ W1_time + b1 ----------------
__global__ void __launch_bounds__(128) te_kernel(const int* __restrict__ t,
                                                 const float* __restrict__ W1,
                                                 const float* __restrict__ b1){
    __shared__ float te[cTE];
    int b = blockIdx.x, tid = threadIdx.x;
    if (tid < 32){
        int ti = t[b]; ti = ti < 0 ? 0 : (ti > cTf-1 ? cTf-1 : ti);
        float invf = expf(-(float)tid * (logf(10000.0f) / 31.0f));
        float fr = (float)ti * invf;
        te[tid]      = sinf(fr);
        te[tid + 32] = cosf(fr);
    }
    __syncthreads();
    float acc = b1[tid];
    #pragma unroll
    for (int e = 0; e < cTE; e++) acc = fmaf(te[e], W1[(2*cE + 2 + cH + e)*cH + tid], acc);
    g_TEW[b*cH + tid] = acc;
}

// ---------------- attention core ----------------
// One block per 8 consecutive n of the same batch. Scores live in registers:
// thread (tf=tid>>4, tm=tid&15) owns rows f0..f0+3, columns m = tm*4 + 64j + c.
__global__ void __launch_bounds__(256, 1) attn_kernel(const int* __restrict__ t,
                                                      float* __restrict__ out_attn,
                                                      float* __restrict__ out_loss){
    extern __shared__ float sm[];
    float* kvT  = sm;                 // 32768 f  [h=128][m=256]
    float* qTs  = sm + 32768;         // 4096 f   [f=64][hh=64] (one h-half)
    float* accS = sm + 36864;         // 16384 f  rotated [f][m]
    float* prow = sm + 53248;         // 256 f
    float* red  = sm + 53504;         // 32 f

    int tid = threadIdx.x, bid = blockIdx.x;
    int b = bid >> 4, nbase = (bid & 15) * NP;
    int tf = tid >> 4, tm = tid & 15;
    int f0 = tf*4, m0 = tm*4;
    int lane = tid & 31;

    // stage kvT, zero accS
    {
        const float4* ks = (const float4*)(g_kvT + (size_t)b*cH*cTm);
        float4* kd = (float4*)kvT;
        #pragma unroll
        for (int i = 0; i < 32; i++) kd[tid + i*256] = ks[tid + i*256];
        float4* az = (float4*)accS;
        float4 z = make_float4(0.f,0.f,0.f,0.f);
        #pragma unroll
        for (int i = 0; i < 16; i++) az[tid + i*256] = z;
    }
    int trow = t[b]; trow = trow < 0 ? 0 : (trow > cTf-1 ? cTf-1 : trow);
    float entacc = 0.f;
    const float scale = 0.08838834764831843f;   // 1/sqrt(128)

    for (int np = 0; np < NP; np++){
        int bn = b*cN + nbase + np;
        ull acc[4][8];
        #pragma unroll
        for (int fi = 0; fi < 4; fi++)
            #pragma unroll
            for (int p = 0; p < 8; p++) acc[fi][p] = 0ull;

        #pragma unroll
        for (int hb = 0; hb < 2; hb++){
            __syncthreads();   // protect qTs (and prow from prev pass)
            {
                const float4* qsrc = (const float4*)(g_q + (size_t)bn*cTf*cH + hb*64);
                float4* qdst = (float4*)qTs;
                #pragma unroll
                for (int k2 = 0; k2 < 4; k2++){
                    int i = tid + k2*256;
                    qdst[(i>>4)*16 + (i&15)] = qsrc[(i>>4)*32 + (i&15)];
                }
            }
            __syncthreads();
            const float* kb2 = kvT + hb*64*256;
            #pragma unroll 2
            for (int h = 0; h < 64; h++){
                ull qq[4];
                #pragma unroll
                for (int fi = 0; fi < 4; fi++) qq[fi] = pack2(qTs[(f0+fi)*64 + h]);
                const float* krow = kb2 + h*256 + m0;
                ulonglong2 ka = *(const ulonglong2*)(krow);
                ulonglong2 kb = *(const ulonglong2*)(krow + 64);
                ulonglong2 kc = *(const ulonglong2*)(krow + 128);
                ulonglong2 kd = *(const ulonglong2*)(krow + 192);
                ull kk[8] = {ka.x, ka.y, kb.x, kb.y, kc.x, kc.y, kd.x, kd.y};
                #pragma unroll
                for (int fi = 0; fi < 4; fi++)
                    #pragma unroll
                    for (int p = 0; p < 8; p++)
                        fma2(acc[fi][p], qq[fi], kk[p]);
            }
        }

        // softmax + entropy + accS accumulate + prow capture (registers -> shfl)
        #pragma unroll
        for (int fi = 0; fi < 4; fi++){
            float v[16];
            #pragma unroll
            for (int p = 0; p < 8; p++){
                float2 t2 = ull2f2(acc[fi][p]);
                v[2*p]   = t2.x * scale;
                v[2*p+1] = t2.y * scale;
            }
            float mx = v[0];
            #pragma unroll
            for (int k = 1; k < 16; k++) mx = fmaxf(mx, v[k]);
            #pragma unroll
            for (int o = 8; o > 0; o >>= 1) mx = fmaxf(mx, __shfl_xor_sync(0xffffffffu, mx, o));
            float Z = 0.f, U = 0.f;
            #pragma unroll
            for (int k = 0; k < 16; k++){
                float u = v[k] - mx;
                float e = __expf(u);
                Z += e; U = fmaf(e, u, U); v[k] = e;
            }
            #pragma unroll
            for (int o = 8; o > 0; o >>= 1){
                Z += __shfl_xor_sync(0xffffffffu, Z, o);
                U += __shfl_xor_sync(0xffffffffu, U, o);
            }
            float inv = __fdividef(1.f, Z);
            if (tm == 0) entacc += __logf(Z) - U*inv;   // = -sum p*log p
            int f = f0 + fi;
            int rot = 4*(f & 7);
            float* arow = accS + f*256;
            bool isT = (f == trow);
            #pragma unroll
            for (int j = 0; j < 4; j++){
                int mlog = m0 + 64*j;
                float4 pj = make_float4(v[4*j]*inv, v[4*j+1]*inv, v[4*j+2]*inv, v[4*j+3]*inv);
                float4* ap = (float4*)(arow + ((mlog + rot) & 255));
                float4 old = *ap;
                old.x += pj.x; old.y += pj.y; old.z += pj.z; old.w += pj.w;
                *ap = old;
                if (isT) *(float4*)(prow + mlog) = pj;
            }
        }
        __syncthreads();   // prow ready

        // ctx for the gathered row only; cond = q[trow] + ctx
        if (tid < 128){
            int h = tid;
            const float* krow = kvT + h*256;
            float cacc = 0.f;
            #pragma unroll 8
            for (int mm = 0; mm < 256; mm++){
                int m = (lane + mm) & 255;
                cacc = fmaf(prow[m], krow[m], cacc);
            }
            float qv = g_q[(size_t)bn*cTf*cH + trow*cH + h];
            g_cond[(size_t)bn*cH + h] = qv + cacc;
        }
    }
    __syncthreads();

    // entropy block reduce -> single atomic
    #pragma unroll
    for (int o = 16; o > 0; o >>= 1) entacc += __shfl_xor_sync(0xffffffffu, entacc, o);
    if (lane == 0) red[tid >> 5] = entacc;
    __syncthreads();
    if (tid == 0){
        float tot = 0.f;
        #pragma unroll
        for (int i = 0; i < 8; i++) tot += red[i];
        atomicAdd(out_loss, tot * (1.f/(float)(cB*cN*cTf)));
    }

    // accS flush -> global (8x fewer atomics than per-pass)
    #pragma unroll 4
    for (int k = 0; k < 64; k++){
        int idx = tid + k*256;
        int f = idx >> 8, m = idx & 255;
        int maddr = (m + 4*(f & 7)) & 255;
        atomicAdd(out_attn + ((size_t)b*cTf + f)*cTm + m, accS[f*256 + maddr] * (1.f/128.f));
    }
}

// ---------------- A = h@W1_hi ; Bv = h@W1_hj + cond@W1_cond + TEW ----------------
__global__ void __launch_bounds__(128) ab_kernel(const float* __restrict__ W1){
    __shared__ float hrow[cE];
    __shared__ float crow[cH];
    int bid = blockIdx.x, tid = threadIdx.x;
    if (tid < cE) hrow[tid] = g_h[(size_t)bid*cE + tid];
    crow[tid] = g_cond[(size_t)bid*cH + tid];
    __syncthreads();
    int b = bid >> 7;
    float a = 0.f, bv = g_TEW[b*cH + tid];
    #pragma unroll 8
    for (int e = 0; e < cE; e++) a = fmaf(hrow[e], W1[e*cH + tid], a);
    #pragma unroll 8
    for (int e = 0; e < cE; e++) bv = fmaf(hrow[e], W1[(cE + e)*cH + tid], bv);
    #pragma unroll 8
    for (int c = 0; c < cH; c++) bv = fmaf(crow[c], W1[(2*cE + 2 + c)*cH + tid], bv);
    g_A[(size_t)bid*cH + tid]  = a;
    g_Bv[(size_t)bid*cH + tid] = bv;
}

// ---------------- final edge MLP ----------------
__global__ void __launch_bounds__(128) final_kernel(const float* __restrict__ adj,
                                                    const float* __restrict__ gpre,
                                                    const float* __restrict__ W1,
                                                    const float* __restrict__ W2,
                                                    const float* __restrict__ b2,
                                                    float* __restrict__ out){
    extern __shared__ float sm[];
    float*  BvS = sm;                              // [j=128][k=128] pitch 129
    float*  A8  = sm + 128*129;                    // [8][128]
    float4* W3  = (float4*)(sm + 128*129 + 1024);  // 128 x (wa, wg, w2, 0)
    int b = blockIdx.y, ic = blockIdx.x, tid = threadIdx.x;
    for (int r = 0; r < cN; r++)
        BvS[r*129 + tid] = g_Bv[((size_t)b*cN + r)*cH + tid];
    #pragma unroll
    for (int ii = 0; ii < 8; ii++)
        A8[ii*128 + tid] = g_A[((size_t)b*cN + ic*8 + ii)*cH + tid];
    W3[tid] = make_float4(W1[(2*cE)*cH + tid], W1[(2*cE + 1)*cH + tid], W2[tid], 0.f);
    float b2v = b2[0];
    __syncthreads();
    const float* brow = BvS + tid*129;
    #pragma unroll
    for (int ii = 0; ii < 8; ii++){
        int i = ic*8 + ii;
        size_t rbase = ((size_t)b*cN + i)*cN + tid;
        float adjv = adj[rbase], gv = gpre[rbase];
        const float* arow = A8 + ii*128;
        float acc = 0.f;
        #pragma unroll 4
        for (int k = 0; k < cH; k++){
            float4 ww = W3[k];
            float pre = arow[k] + brow[k] + adjv*ww.x + gv*ww.y;
            acc = fmaf(fmaxf(pre, 0.f), ww.z, acc);
        }
        out[rbase] = acc + b2v;
    }
}

// ---------------- launch ----------------
extern "C" void kernel_launch(void* const* d_in, const int* in_sizes, int n_in,
                              void* d_out, int out_size){
    const float* noisy_adj  = (const float*)d_in[0];
    const float* node_feats = (const float*)d_in[1];
    const float* feat_fnirs = (const float*)d_in[2];
    const float* feat_music = (const float*)d_in[3];
    const float* g_pre      = (const float*)d_in[4];
    const float* node_W     = (const float*)d_in[5];
    const float* node_b     = (const float*)d_in[6];
    const float* fnirs_W    = (const float*)d_in[7];
    const float* fnirs_b    = (const float*)d_in[8];
    const float* music_W    = (const float*)d_in[9];
    const float* music_b    = (const float*)d_in[10];
    const float* mlp_W1     = (const float*)d_in[11];
    const float* mlp_b1     = (const float*)d_in[12];
    const float* mlp_W2     = (const float*)d_in[13];
    const float* mlp_b2     = (const float*)d_in[14];
    const int*   t          = (const int*)d_in[15];

    float* out      = (float*)d_out;
    float* out_attn = out + cB*cN*cN;
    float* out_loss = out + cB*cN*cN + cB*cTf*cTm;

    cudaFuncSetAttribute(kv_kernel,    cudaFuncAttributeMaxDynamicSharedMemorySize, 131584);
    cudaFuncSetAttribute(attn_kernel,  cudaFuncAttributeMaxDynamicSharedMemorySize, 214144);
    cudaFuncSetAttribute(final_kernel, cudaFuncAttributeMaxDynamicSharedMemorySize, 72192);

    cudaMemsetAsync(out_attn, 0, (size_t)(cB*cTf*cTm + 1)*sizeof(float));

    kv_kernel<<<dim3(8, cB), 256, 131584>>>(feat_music, music_W, music_b);
    qpre_kernel<<<cB*cN, 128>>>(feat_fnirs, fnirs_W, fnirs_b);
    h_kernel<<<cB*cN, 64>>>(node_feats, node_W, node_b);
    te_kernel<<<cB, 128>>>(t, mlp_W1, mlp_b1);
    attn_kernel<<<(cB*cN)/NP, 256, 214144>>>(t, out_attn, out_loss);
    ab_kernel<<<cB*cN, 128>>>(mlp_W1);
    final_kernel<<<dim3(16, cB), 128, 72192>>>(noisy_adj, g_pre, mlp_W1, mlp_W2, mlp_b2, out);
}

// round 3
// speedup vs baseline: 1.3977x; 1.0060x over previous
#include <cuda_runtime.h>
#include <math.h>

#define cB 8
#define cN 128
#define cF 128
#define cTf 64
#define cTm 256
#define cDf 32
#define cDm 128
#define cE 64
#define cH 128
#define cTE 64
#define NP 8

typedef unsigned long long ull;

// ---------------- device scratch ----------------
__device__ float g_kvT[cB*cH*cTm];        // [b][h][m]
__device__ float g_q[cB*cN*cTf*cH];       // [b][n][f][h]
__device__ float g_cond[cB*cN*cH];
__device__ float g_h[cB*cN*cE];
__device__ float g_TEW[cB*cH];
__device__ float g_A[cB*cN*cH];
__device__ float g_Bv[cB*cN*cH];

// ---------------- packed f32x2 helpers ----------------
__device__ __forceinline__ ull pack2(float x){
    ull r; asm("mov.b64 %0, {%1, %1};" : "=l"(r) : "f"(x)); return r;
}
__device__ __forceinline__ ull packab(float a, float b){
    ull r; asm("mov.b64 %0, {%1, %2};" : "=l"(r) : "f"(a), "f"(b)); return r;
}
__device__ __forceinline__ void fma2(ull &acc, ull a, ull b){
    asm("fma.rn.f32x2 %0, %1, %2, %0;" : "+l"(acc) : "l"(a), "l"(b));
}
__device__ __forceinline__ float2 ull2f2(ull v){
    float2 f; asm("mov.b64 {%0, %1}, %2;" : "=f"(f.x), "=f"(f.y) : "l"(v)); return f;
}

// ---------------- kv = feat_music @ music_W + music_b (transposed) ----------------
__global__ void __launch_bounds__(256) kv_kernel(const float* __restrict__ music,
                                                 const float* __restrict__ W,
                                                 const float* __restrict__ bias){
    extern __shared__ float sm[];            // musT [d=128][m=256] pitch 257
    int b  = blockIdx.y;
    int hc = blockIdx.x;
    int tid = threadIdx.x;
    for (int idx = tid; idx < cTm*cDm; idx += 256){
        int m = idx >> 7, d = idx & 127;
        sm[d*257 + m] = music[((size_t)b*cTm + m)*cDm + d];
    }
    __syncthreads();
    int m = tid;
    for (int hh = 0; hh < 16; hh++){
        int h = hc*16 + hh;
        float acc = bias[h];
        #pragma unroll 8
        for (int d = 0; d < cDm; d++)
            acc = fmaf(sm[d*257 + m], W[d*cH + h], acc);
        g_kvT[((size_t)b*cH + h)*cTm + m] = acc;
    }
}

// ---------------- q precompute: g_q[b][n][f][h] ----------------
__global__ void __launch_bounds__(128) qpre_kernel(const float* __restrict__ feat,
                                                   const float* __restrict__ W,
                                                   const float* __restrict__ bias){
    __shared__ float sfeat[cTf*cDf];          // 2048 floats
    int bn = blockIdx.x, tid = threadIdx.x;
    {
        const float4* fs = (const float4*)(feat + (size_t)bn*cTf*cDf);
        float4* fd = (float4*)sfeat;
        #pragma unroll
        for (int i = tid; i < 512; i += 128) fd[i] = fs[i];
    }
    float w[cDf];
    #pragma unroll
    for (int d = 0; d < cDf; d++) w[d] = W[d*cH + tid];
    float bs = bias[tid];
    __syncthreads();
    float* qbase = g_q + (size_t)bn*cTf*cH;
    for (int j = 0; j < 32; j++){
        ull acc = pack2(bs);
        const float* ra = sfeat + (2*j)*cDf;
        const float* rb = sfeat + (2*j+1)*cDf;
        #pragma unroll
        for (int d = 0; d < cDf; d++)
            fma2(acc, packab(ra[d], rb[d]), pack2(w[d]));
        float2 q2 = ull2f2(acc);
        qbase[(2*j)*cH + tid]   = q2.x;
        qbase[(2*j+1)*cH + tid] = q2.y;
    }
}

// ---------------- h = node_feats @ node_W + node_b ----------------
__global__ void __launch_bounds__(64) h_kernel(const float* __restrict__ nf,
                                               const float* __restrict__ Wn,
                                               const float* __restrict__ bn){
    __shared__ float row[cF];
    int bid = blockIdx.x, tid = threadIdx.x;
    row[tid]      = nf[(size_t)bid*cF + tid];
    row[tid + 64] = nf[(size_t)bid*cF + tid + 64];
    __syncthreads();
    float acc = bn[tid];
    #pragma unroll 8
    for (int f = 0; f < cF; f++) acc = fmaf(row[f], Wn[f*cE + tid], acc);
    g_h[(size_t)bid*cE + tid] = acc;
}

// ---------------- TEW[b,k] = time_emb(t[b]) @ W1_time + b1 ----------------
__global__ void __launch_bounds__(128) te_kernel(const int* __restrict__ t,
                                                 const float* __restrict__ W1,
                                                 const float* __restrict__ b1){
    __shared__ float te[cTE];
    int b = blockIdx.x, tid = threadIdx.x;
    if (tid < 32){
        int ti = t[b]; ti = ti < 0 ? 0 : (ti > cTf-1 ? cTf-1 : ti);
        float invf = expf(-(float)tid * (logf(10000.0f) / 31.0f));
        float fr = (float)ti * invf;
        te[tid]      = sinf(fr);
        te[tid + 32] = cosf(fr);
    }
    __syncthreads();
    float acc = b1[tid];
    #pragma unroll
    for (int e = 0; e < cTE; e++) acc = fmaf(te[e], W1[(2*cE + 2 + cH + e)*cH + tid], acc);
    g_TEW[b*cH + tid] = acc;
}

// ---------------- attention core ----------------
// One block per 8 consecutive n of the same batch. Scores live in registers:
// thread (tf=tid>>4, tm=tid&15) owns rows f0..f0+3, columns m = tm*4 + 64j + c.
__global__ void __launch_bounds__(256, 1) attn_kernel(const int* __restrict__ t,
                                                      float* __restrict__ out_attn,
                                                      float* __restrict__ out_loss){
    extern __shared__ float sm[];
    float* kvT  = sm;                 // 32768 f  [h=128][m=256]
    float* qTs  = sm + 32768;         // 4096 f   [f=64][hh=64] (one h-half)
    float* accS = sm + 36864;         // 16384 f  rotated [f][m]
    float* prow = sm + 53248;         // 256 f
    float* red  = sm + 53504;         // 32 f

    int tid = threadIdx.x, bid = blockIdx.x;
    int b = bid >> 4, nbase = (bid & 15) * NP;
    int tf = tid >> 4, tm = tid & 15;
    int f0 = tf*4, m0 = tm*4;
    int lane = tid & 31;

    // stage kvT, zero accS
    {
        const float4* ks = (const float4*)(g_kvT + (size_t)b*cH*cTm);
        float4* kd = (float4*)kvT;
        #pragma unroll
        for (int i = 0; i < 32; i++) kd[tid + i*256] = ks[tid + i*256];
        float4* az = (float4*)accS;
        float4 z = make_float4(0.f,0.f,0.f,0.f);
        #pragma unroll
        for (int i = 0; i < 16; i++) az[tid + i*256] = z;
    }
    int trow = t[b]; trow = trow < 0 ? 0 : (trow > cTf-1 ? cTf-1 : trow);
    float entacc = 0.f;
    const float scale = 0.08838834764831843f;   // 1/sqrt(128)

    for (int np = 0; np < NP; np++){
        int bn = b*cN + nbase + np;
        ull acc[4][8];
        #pragma unroll
        for (int fi = 0; fi < 4; fi++)
            #pragma unroll
            for (int p = 0; p < 8; p++) acc[fi][p] = 0ull;

        #pragma unroll
        for (int hb = 0; hb < 2; hb++){
            __syncthreads();   // protect qTs (and prow from prev pass)
            {
                const float4* qsrc = (const float4*)(g_q + (size_t)bn*cTf*cH + hb*64);
                float4* qdst = (float4*)qTs;
                #pragma unroll
                for (int k2 = 0; k2 < 4; k2++){
                    int i = tid + k2*256;
                    qdst[(i>>4)*16 + (i&15)] = qsrc[(i>>4)*32 + (i&15)];
                }
            }
            __syncthreads();
            const float* kb2 = kvT + hb*64*256;
            #pragma unroll 2
            for (int h = 0; h < 64; h++){
                ull qq[4];
                #pragma unroll
                for (int fi = 0; fi < 4; fi++) qq[fi] = pack2(qTs[(f0+fi)*64 + h]);
                const float* krow = kb2 + h*256 + m0;
                ulonglong2 ka = *(const ulonglong2*)(krow);
                ulonglong2 kb = *(const ulonglong2*)(krow + 64);
                ulonglong2 kc = *(const ulonglong2*)(krow + 128);
                ulonglong2 kd = *(const ulonglong2*)(krow + 192);
                ull kk[8] = {ka.x, ka.y, kb.x, kb.y, kc.x, kc.y, kd.x, kd.y};
                #pragma unroll
                for (int fi = 0; fi < 4; fi++)
                    #pragma unroll
                    for (int p = 0; p < 8; p++)
                        fma2(acc[fi][p], qq[fi], kk[p]);
            }
        }

        // softmax + entropy + accS accumulate + prow capture (registers -> shfl)
        #pragma unroll
        for (int fi = 0; fi < 4; fi++){
            float v[16];
            #pragma unroll
            for (int p = 0; p < 8; p++){
                float2 t2 = ull2f2(acc[fi][p]);
                v[2*p]   = t2.x * scale;
                v[2*p+1] = t2.y * scale;
            }
            float mx = v[0];
            #pragma unroll
            for (int k = 1; k < 16; k++) mx = fmaxf(mx, v[k]);
            #pragma unroll
            for (int o = 8; o > 0; o >>= 1) mx = fmaxf(mx, __shfl_xor_sync(0xffffffffu, mx, o));
            float Z = 0.f, U = 0.f;
            #pragma unroll
            for (int k = 0; k < 16; k++){
                float u = v[k] - mx;
                float e = __expf(u);
                Z += e; U = fmaf(e, u, U); v[k] = e;
            }
            #pragma unroll
            for (int o = 8; o > 0; o >>= 1){
                Z += __shfl_xor_sync(0xffffffffu, Z, o);
                U += __shfl_xor_sync(0xffffffffu, U, o);
            }
            float inv = __fdividef(1.f, Z);
            if (tm == 0) entacc += __logf(Z) - U*inv;   // = -sum p*log p
            int f = f0 + fi;
            int rot = 4*(f & 7);
            float* arow = accS + f*256;
            bool isT = (f == trow);
            #pragma unroll
            for (int j = 0; j < 4; j++){
                int mlog = m0 + 64*j;
                float4 pj = make_float4(v[4*j]*inv, v[4*j+1]*inv, v[4*j+2]*inv, v[4*j+3]*inv);
                float4* ap = (float4*)(arow + ((mlog + rot) & 255));
                float4 old = *ap;
                old.x += pj.x; old.y += pj.y; old.z += pj.z; old.w += pj.w;
                *ap = old;
                if (isT) *(float4*)(prow + mlog) = pj;
            }
        }
        __syncthreads();   // prow ready

        // ctx for the gathered row only; cond = q[trow] + ctx
        if (tid < 128){
            int h = tid;
            const float* krow = kvT + h*256;
            float cacc = 0.f;
            #pragma unroll 8
            for (int mm = 0; mm < 256; mm++){
                int m = (lane + mm) & 255;
                cacc = fmaf(prow[m], krow[m], cacc);
            }
            float qv = g_q[(size_t)bn*cTf*cH + trow*cH + h];
            g_cond[(size_t)bn*cH + h] = qv + cacc;
        }
    }
    __syncthreads();

    // entropy block reduce -> single atomic
    #pragma unroll
    for (int o = 16; o > 0; o >>= 1) entacc += __shfl_xor_sync(0xffffffffu, entacc, o);
    if (lane == 0) red[tid >> 5] = entacc;
    __syncthreads();
    if (tid == 0){
        float tot = 0.f;
        #pragma unroll
        for (int i = 0; i < 8; i++) tot += red[i];
        atomicAdd(out_loss, tot * (1.f/(float)(cB*cN*cTf)));
    }

    // accS flush -> global (8x fewer atomics than per-pass)
    #pragma unroll 4
    for (int k = 0; k < 64; k++){
        int idx = tid + k*256;
        int f = idx >> 8, m = idx & 255;
        int maddr = (m + 4*(f & 7)) & 255;
        atomicAdd(out_attn + ((size_t)b*cTf + f)*cTm + m, accS[f*256 + maddr] * (1.f/128.f));
    }
}

// ---------------- A = h@W1_hi ; Bv = h@W1_hj + cond@W1_cond + TEW ----------------
__global__ void __launch_bounds__(128) ab_kernel(const float* __restrict__ W1){
    __shared__ float hrow[cE];
    __shared__ float crow[cH];
    int bid = blockIdx.x, tid = threadIdx.x;
    if (tid < cE) hrow[tid] = g_h[(size_t)bid*cE + tid];
    crow[tid] = g_cond[(size_t)bid*cH + tid];
    __syncthreads();
    int b = bid >> 7;
    float a = 0.f, bv = g_TEW[b*cH + tid];
    #pragma unroll 8
    for (int e = 0; e < cE; e++) a = fmaf(hrow[e], W1[e*cH + tid], a);
    #pragma unroll 8
    for (int e = 0; e < cE; e++) bv = fmaf(hrow[e], W1[(cE + e)*cH + tid], bv);
    #pragma unroll 8
    for (int c = 0; c < cH; c++) bv = fmaf(crow[c], W1[(2*cE + 2 + c)*cH + tid], bv);
    g_A[(size_t)bid*cH + tid]  = a;
    g_Bv[(size_t)bid*cH + tid] = bv;
}

// ---------------- final edge MLP ----------------
__global__ void __launch_bounds__(128) final_kernel(const float* __restrict__ adj,
                                                    const float* __restrict__ gpre,
                                                    const float* __restrict__ W1,
                                                    const float* __restrict__ W2,
                                                    const float* __restrict__ b2,
                                                    float* __restrict__ out){
    extern __shared__ float sm[];
    float*  BvS = sm;                              // [j=128][k=128] pitch 129
    float*  A8  = sm + 128*129;                    // [8][128]
    float4* W3  = (float4*)(sm + 128*129 + 1024);  // 128 x (wa, wg, w2, 0)
    int b = blockIdx.y, ic = blockIdx.x, tid = threadIdx.x;
    for (int r = 0; r < cN; r++)
        BvS[r*129 + tid] = g_Bv[((size_t)b*cN + r)*cH + tid];
    #pragma unroll
    for (int ii = 0; ii < 8; ii++)
        A8[ii*128 + tid] = g_A[((size_t)b*cN + ic*8 + ii)*cH + tid];
    W3[tid] = make_float4(W1[(2*cE)*cH + tid], W1[(2*cE + 1)*cH + tid], W2[tid], 0.f);
    float b2v = b2[0];
    __syncthreads();
    const float* brow = BvS + tid*129;
    #pragma unroll
    for (int ii = 0; ii < 8; ii++){
        int i = ic*8 + ii;
        size_t rbase = ((size_t)b*cN + i)*cN + tid;
        float adjv = adj[rbase], gv = gpre[rbase];
        const float* arow = A8 + ii*128;
        float acc = 0.f;
        #pragma unroll 4
        for (int k = 0; k < cH; k++){
            float4 ww = W3[k];
            float pre = arow[k] + brow[k] + adjv*ww.x + gv*ww.y;
            acc = fmaf(fmaxf(pre, 0.f), ww.z, acc);
        }
        out[rbase] = acc + b2v;
    }
}

// ---------------- launch ----------------
extern "C" void kernel_launch(void* const* d_in, const int* in_sizes, int n_in,
                              void* d_out, int out_size){
    const float* noisy_adj  = (const float*)d_in[0];
    const float* node_feats = (const float*)d_in[1];
    const float* feat_fnirs = (const float*)d_in[2];
    const float* feat_music = (const float*)d_in[3];
    const float* g_pre      = (const float*)d_in[4];
    const float* node_W     = (const float*)d_in[5];
    const float* node_b     = (const float*)d_in[6];
    const float* fnirs_W    = (const float*)d_in[7];
    const float* fnirs_b    = (const float*)d_in[8];
    const float* music_W    = (const float*)d_in[9];
    const float* music_b    = (const float*)d_in[10];
    const float* mlp_W1     = (const float*)d_in[11];
    const float* mlp_b1     = (const float*)d_in[12];
    const float* mlp_W2     = (const float*)d_in[13];
    const float* mlp_b2     = (const float*)d_in[14];
    const int*   t          = (const int*)d_in[15];

    float* out      = (float*)d_out;
    float* out_attn = out + cB*cN*cN;
    float* out_loss = out + cB*cN*cN + cB*cTf*cTm;

    cudaFuncSetAttribute(kv_kernel,    cudaFuncAttributeMaxDynamicSharedMemorySize, 131584);
    cudaFuncSetAttribute(attn_kernel,  cudaFuncAttributeMaxDynamicSharedMemorySize, 214144);
    cudaFuncSetAttribute(final_kernel, cudaFuncAttributeMaxDynamicSharedMemorySize, 72192);

    cudaMemsetAsync(out_attn, 0, (size_t)(cB*cTf*cTm + 1)*sizeof(float));

    kv_kernel<<<dim3(8, cB), 256, 131584>>>(feat_music, music_W, music_b);
    qpre_kernel<<<cB*cN, 128>>>(feat_fnirs, fnirs_W, fnirs_b);
    h_kernel<<<cB*cN, 64>>>(node_feats, node_W, node_b);
    te_kernel<<<cB, 128>>>(t, mlp_W1, mlp_b1);
    attn_kernel<<<(cB*cN)/NP, 256, 214144>>>(t, out_attn, out_loss);
    ab_kernel<<<cB*cN, 128>>>(mlp_W1);
    final_kernel<<<dim3(16, cB), 128, 72192>>>(noisy_adj, g_pre, mlp_W1, mlp_W2, mlp_b2, out);
}

// round 5
// speedup vs baseline: 2.3821x; 1.7043x over previous
#include <cuda_runtime.h>
#include <cuda_bf16.h>
#include <math.h>
#include <stdint.h>

#define cB 8
#define cN 128
#define cF 128
#define cTf 64
#define cTm 256
#define cDf 32
#define cDm 128
#define cE 64
#define cH 128
#define QSCALE 0.08838834764831843f

typedef unsigned long long ull;

// ---------------- device scratch ----------------
__device__ __align__(16) unsigned char g_kvB[cB*65536];     // per b: swizzled [m=256][h=128] bf16
__device__ __align__(16) unsigned char g_qA[cB*cN*16384];   // per n: swizzled [f=64][h=128] bf16 (q*scale)
__device__ float g_qt[cB*cN*cH];                            // q at t-row (fp32)
__device__ float g_cond[cB*cN*cH];                          // ctx at t-row
__device__ float g_A[cB*cN*cH];
__device__ float g_Bv[cB*cN*cH];

// ---------------- helpers ----------------
__device__ __forceinline__ uint32_t smem_u32(const void* p){
    uint32_t a;
    asm("{ .reg .u64 t; cvta.to.shared.u64 t, %1; cvt.u32.u64 %0, t; }" : "=r"(a) : "l"(p));
    return a;
}
// swizzled byte offset in tile of R rows x 128 bf16 cols (atom_rows = R/8, 2 atom-cols)
__device__ __forceinline__ uint32_t tile_off(int r, int c, int atom_rows){
    uint32_t boff = (uint32_t)((r>>3) + (c>>6)*atom_rows)*1024u + (uint32_t)(r&7)*128u + (uint32_t)(c&63)*2u;
    return boff ^ ((boff >> 3) & 0x70u);
}
#define LDM_X4(r, a) \
    asm volatile("ldmatrix.sync.aligned.m8n8.x4.shared.b16 {%0,%1,%2,%3}, [%4];" \
        : "=r"((r)[0]),"=r"((r)[1]),"=r"((r)[2]),"=r"((r)[3]) : "r"(a))

__device__ __forceinline__ void mma_bf16(float* c, const uint32_t* a, uint32_t b0, uint32_t b1){
    asm volatile("mma.sync.aligned.m16n8k16.row.col.f32.bf16.bf16.f32 "
        "{%0,%1,%2,%3}, {%4,%5,%6,%7}, {%8,%9}, {%0,%1,%2,%3};"
        : "+f"(c[0]),"+f"(c[1]),"+f"(c[2]),"+f"(c[3])
        : "r"(a[0]),"r"(a[1]),"r"(a[2]),"r"(a[3]), "r"(b0),"r"(b1));
}

// packed f32x2
__device__ __forceinline__ ull pack2(float x){ ull r; asm("mov.b64 %0, {%1, %1};" : "=l"(r) : "f"(x)); return r; }
__device__ __forceinline__ ull packab(float a, float b){ ull r; asm("mov.b64 %0, {%1, %2};" : "=l"(r) : "f"(a), "f"(b)); return r; }
__device__ __forceinline__ void fma2(ull &acc, ull a, ull b){ asm("fma.rn.f32x2 %0, %1, %2, %0;" : "+l"(acc) : "l"(a), "l"(b)); }
__device__ __forceinline__ float2 u2f2(ull v){ float2 f; asm("mov.b64 {%0, %1}, %2;" : "=f"(f.x), "=f"(f.y) : "l"(v)); return f; }

// ---------------- kv -> bf16 swizzled tile ----------------
__global__ void __launch_bounds__(256) kv_kernel(const float* __restrict__ music,
                                                 const float* __restrict__ W,
                                                 const float* __restrict__ bias){
    extern __shared__ float sm[];            // musT [d=128][m=256] pitch 257
    int b  = blockIdx.y, hc = blockIdx.x, tid = threadIdx.x;
    for (int idx = tid; idx < cTm*cDm; idx += 256){
        int m = idx >> 7, d = idx & 127;
        sm[d*257 + m] = music[((size_t)b*cTm + m)*cDm + d];
    }
    __syncthreads();
    int m = tid;
    unsigned char* tb = g_kvB + (size_t)b*65536;
    for (int hh = 0; hh < 16; hh++){
        int h = hc*16 + hh;
        float acc = bias[h];
        #pragma unroll 8
        for (int d = 0; d < cDm; d++)
            acc = fmaf(sm[d*257 + m], W[d*cH + h], acc);
        *(__nv_bfloat16*)(tb + tile_off(m, h, 32)) = __float2bfloat16(acc);
    }
}

// ---------------- q -> bf16 scaled tile (per n) + t-row fp32 ----------------
__global__ void __launch_bounds__(128) qpre_kernel(const float* __restrict__ feat,
                                                   const float* __restrict__ W,
                                                   const float* __restrict__ bias,
                                                   const int* __restrict__ t){
    __shared__ float sfeat[cTf*cDf];
    int bn = blockIdx.x, tid = threadIdx.x;
    int b = bn >> 7;
    int trow = t[b]; trow = trow < 0 ? 0 : (trow > cTf-1 ? cTf-1 : trow);
    {
        const float4* fs = (const float4*)(feat + (size_t)bn*cTf*cDf);
        float4* fd = (float4*)sfeat;
        #pragma unroll
        for (int i = tid; i < 512; i += 128) fd[i] = fs[i];
    }
    float w[cDf];
    #pragma unroll
    for (int d = 0; d < cDf; d++) w[d] = W[d*cH + tid];
    float bs = bias[tid];
    __syncthreads();
    unsigned char* tb = g_qA + (size_t)bn*16384;
    for (int j = 0; j < 32; j++){
        ull acc = pack2(bs);
        const float* ra = sfeat + (2*j)*cDf;
        const float* rb = sfeat + (2*j+1)*cDf;
        #pragma unroll
        for (int d = 0; d < cDf; d++)
            fma2(acc, packab(ra[d], rb[d]), pack2(w[d]));
        float2 q2 = u2f2(acc);
        if (2*j   == trow) g_qt[(size_t)bn*cH + tid] = q2.x;
        if (2*j+1 == trow) g_qt[(size_t)bn*cH + tid] = q2.y;
        *(__nv_bfloat16*)(tb + tile_off(2*j,   tid, 8)) = __float2bfloat16(q2.x * QSCALE);
        *(__nv_bfloat16*)(tb + tile_off(2*j+1, tid, 8)) = __float2bfloat16(q2.y * QSCALE);
    }
}

// ---------------- attention (mma.sync bf16) ----------------
#define SM_B    0
#define SM_A    65536
#define SM_ZU   98304
#define SM_PROW 100352
#define SM_RED  108544
#define ATTN_SMEM 108800

__global__ void __launch_bounds__(256, 1) attn_kernel(const int* __restrict__ t,
                                                      float* __restrict__ out_attn,
                                                      float* __restrict__ out_loss){
    extern __shared__ char smem[];
    uint32_t sbase = smem_u32(smem);
    float2* zu    = (float2*)(smem + SM_ZU);    // [64 rows][4 wm]
    float*  prowS = (float*)(smem + SM_PROW);   // [8 n][256 m]
    float*  red   = (float*)(smem + SM_RED);

    int tid = threadIdx.x, wid = tid >> 5, lane = tid & 31;
    int b = blockIdx.x >> 4, nbase = (blockIdx.x & 15) * 8;
    int wf = wid >> 2, wm = wid & 3;            // warp grid 2 (f) x 4 (m)
    int f0 = wf*32, m0 = wm*64;
    int qr = lane >> 2, qc = lane & 3;          // quad row/col

    // stage kv (64KB) and q[n0]
    {
        const float4* bs = (const float4*)(g_kvB + (size_t)b*65536);
        float4* bd = (float4*)(smem + SM_B);
        #pragma unroll
        for (int i = 0; i < 16; i++) bd[tid + i*256] = bs[tid + i*256];
        const float4* as = (const float4*)(g_qA + (size_t)(b*cN + nbase)*16384);
        float4* ad = (float4*)(smem + SM_A);
        #pragma unroll
        for (int i = 0; i < 4; i++) ad[tid + i*256] = as[tid + i*256];
    }
    __syncthreads();

    int trow = t[b]; trow = trow < 0 ? 0 : (trow > cTf-1 ? cTf-1 : trow);
    float entacc = 0.f;
    float accW[2][8][4];
    #pragma unroll
    for (int mt = 0; mt < 2; mt++)
        #pragma unroll
        for (int nt = 0; nt < 8; nt++)
            #pragma unroll
            for (int i = 0; i < 4; i++) accW[mt][nt][i] = 0.f;

    // precomputed ldmatrix row/col pieces
    int arow = (lane & 15), acolk = (lane >> 4) * 8;
    int brow = ((lane >> 4) & 1) * 8 + (lane & 7), bcolk = ((lane >> 3) & 1) * 8;

    for (int np = 0; np < 8; np++){
        __syncthreads();
        if (np < 7){
            const float4* as = (const float4*)(g_qA + (size_t)(b*cN + nbase + np + 1)*16384);
            float4* ad = (float4*)(smem + SM_A + ((np+1)&1)*16384);
            #pragma unroll
            for (int i = 0; i < 4; i++) ad[tid + i*256] = as[tid + i*256];
        }
        uint32_t smA = sbase + SM_A + (np&1)*16384;
        uint32_t smB = sbase + SM_B;

        float C[2][8][4];
        #pragma unroll
        for (int mt = 0; mt < 2; mt++)
            #pragma unroll
            for (int nt = 0; nt < 8; nt++)
                #pragma unroll
                for (int i = 0; i < 4; i++) C[mt][nt][i] = 0.f;

        #pragma unroll
        for (int kk = 0; kk < 8; kk++){
            int k0 = kk*16;
            uint32_t a0[4], a1[4], bb[4][4];
            LDM_X4(a0, smA + tile_off(f0 + arow,      k0 + acolk, 8));
            LDM_X4(a1, smA + tile_off(f0 + 16 + arow, k0 + acolk, 8));
            #pragma unroll
            for (int nt2 = 0; nt2 < 4; nt2++)
                LDM_X4(bb[nt2], smB + tile_off(m0 + nt2*16 + brow, k0 + bcolk, 32));
            #pragma unroll
            for (int nt = 0; nt < 8; nt++){
                uint32_t b0 = bb[nt>>1][(nt&1)*2], b1 = bb[nt>>1][(nt&1)*2 + 1];
                mma_bf16(C[0][nt], a0, b0, b1);
                mma_bf16(C[1][nt], a1, b0, b1);
            }
        }

        // ---- epilogue on fragments ----
        // rows per lane: g in 0..3 -> f = f0 + (g>>1)*16 + qr + 8*(g&1), elem idx (g&1)*2 + c
        float Zr[4], Ur[4];
        #pragma unroll
        for (int g = 0; g < 4; g++){
            int mt = g >> 1, pr = g & 1;
            float Z = 0.f, U = 0.f;
            #pragma unroll
            for (int nt = 0; nt < 8; nt++){
                #pragma unroll
                for (int c = 0; c < 2; c++){
                    float v = C[mt][nt][pr*2 + c];
                    float e = __expf(v);
                    Z += e; U = fmaf(e, v, U);
                    C[mt][nt][pr*2 + c] = e;
                }
            }
            #pragma unroll
            for (int o = 1; o <= 2; o <<= 1){
                Z += __shfl_xor_sync(0xffffffffu, Z, o);
                U += __shfl_xor_sync(0xffffffffu, U, o);
            }
            Zr[g] = Z; Ur[g] = U;
            if (qc == 0){
                int f = f0 + mt*16 + qr + 8*pr;
                zu[f*4 + wm] = make_float2(Z, U);
            }
        }
        __syncthreads();
        #pragma unroll
        for (int g = 0; g < 4; g++){
            int mt = g >> 1, pr = g & 1;
            int f = f0 + mt*16 + qr + 8*pr;
            float2 z0 = zu[f*4+0], z1 = zu[f*4+1], z2 = zu[f*4+2], z3 = zu[f*4+3];
            float Zt = z0.x + z1.x + z2.x + z3.x;
            float Ut = z0.y + z1.y + z2.y + z3.y;
            float inv = __fdividef(1.f, Zt);
            if (wm == 0 && qc == 0) entacc += __logf(Zt) - Ut*inv;
            bool isT = (f == trow);
            #pragma unroll
            for (int nt = 0; nt < 8; nt++){
                #pragma unroll
                for (int c = 0; c < 2; c++){
                    float p = C[mt][nt][pr*2 + c] * inv;
                    accW[mt][nt][pr*2 + c] += p;
                    if (isT) prowS[np*256 + m0 + nt*8 + 2*qc + c] = p;
                }
            }
        }
    }
    __syncthreads();

    // ---- ctx for the 8 t-rows from bf16 kv tile ----
    {
        int g = tid >> 7, h = tid & 127;
        uint32_t hbase = (uint32_t)(h >> 6)*32768u;
        uint32_t hlow  = (uint32_t)((h & 63)*2);
        uint32_t offj[8];
        #pragma unroll
        for (int j = 0; j < 8; j++) offj[j] = (uint32_t)(j*128) + (hlow ^ (uint32_t)(j<<4));
        float c0=0.f, c1=0.f, c2=0.f, c3=0.f;
        const float* pr = prowS + g*4*256;
        for (int mg = 0; mg < 32; mg++){
            uint32_t abase = hbase + (uint32_t)mg*1024u;
            #pragma unroll
            for (int j = 0; j < 8; j++){
                unsigned short u = *(const unsigned short*)(smem + SM_B + abase + offj[j]);
                float kvv = __bfloat162float(*reinterpret_cast<__nv_bfloat16*>(&u));
                int m = mg*8 + j;
                c0 = fmaf(pr[m],       kvv, c0);
                c1 = fmaf(pr[256 + m], kvv, c1);
                c2 = fmaf(pr[512 + m], kvv, c2);
                c3 = fmaf(pr[768 + m], kvv, c3);
            }
        }
        size_t cb = ((size_t)b*cN + nbase + 4*g)*cH + h;
        g_cond[cb]        = c0;
        g_cond[cb + cH]   = c1;
        g_cond[cb + 2*cH] = c2;
        g_cond[cb + 3*cH] = c3;
    }

    // entropy -> one atomic
    #pragma unroll
    for (int o = 16; o > 0; o >>= 1) entacc += __shfl_xor_sync(0xffffffffu, entacc, o);
    if (lane == 0) red[wid] = entacc;
    __syncthreads();
    if (tid == 0){
        float tot = 0.f;
        #pragma unroll
        for (int i = 0; i < 8; i++) tot += red[i];
        atomicAdd(out_loss, tot * (1.f/(float)(cB*cN*cTf)));
    }

    // attn-weights flush from registers
    #pragma unroll
    for (int mt = 0; mt < 2; mt++)
        #pragma unroll
        for (int nt = 0; nt < 8; nt++)
            #pragma unroll
            for (int i = 0; i < 4; i++){
                int f = f0 + mt*16 + qr + 8*(i>>1);
                int m = m0 + nt*8 + 2*qc + (i&1);
                atomicAdd(out_attn + ((size_t)b*cTf + f)*cTm + m, accW[mt][nt][i] * (1.f/128.f));
            }
}

// ---------------- ab: node GEMM + time emb + A/Bv ----------------
__global__ void __launch_bounds__(128) ab_kernel(const float* __restrict__ nf,
                                                 const float* __restrict__ Wn,
                                                 const float* __restrict__ bn,
                                                 const int* __restrict__ t,
                                                 const float* __restrict__ W1,
                                                 const float* __restrict__ b1){
    __shared__ float nfs[cF], hrow[cE], crow[cH], tes[64];
    int bid = blockIdx.x, tid = threadIdx.x;
    int b = bid >> 7;
    nfs[tid] = nf[(size_t)bid*cF + tid];
    crow[tid] = g_qt[(size_t)bid*cH + tid] + g_cond[(size_t)bid*cH + tid];
    if (tid < 32){
        int ti = t[b]; ti = ti < 0 ? 0 : (ti > cTf-1 ? cTf-1 : ti);
        float invf = expf(-(float)tid * (logf(10000.0f) / 31.0f));
        float fr = (float)ti * invf;
        tes[tid]      = sinf(fr);
        tes[tid + 32] = cosf(fr);
    }
    __syncthreads();
    if (tid < cE){
        float a = bn[tid];
        #pragma unroll 8
        for (int ff = 0; ff < cF; ff++) a = fmaf(nfs[ff], Wn[ff*cE + tid], a);
        hrow[tid] = a;
    }
    __syncthreads();
    float a = 0.f, bv = b1[tid];
    #pragma unroll
    for (int e = 0; e < 64; e++) bv = fmaf(tes[e], W1[(2*cE + 2 + cH + e)*cH + tid], bv);
    #pragma unroll 8
    for (int e = 0; e < cE; e++) a  = fmaf(hrow[e], W1[e*cH + tid], a);
    #pragma unroll 8
    for (int e = 0; e < cE; e++) bv = fmaf(hrow[e], W1[(cE + e)*cH + tid], bv);
    #pragma unroll 8
    for (int c = 0; c < cH; c++) bv = fmaf(crow[c], W1[(2*cE + 2 + c)*cH + tid], bv);
    g_A[(size_t)bid*cH + tid]  = a;
    g_Bv[(size_t)bid*cH + tid] = bv;
}

// ---------------- final edge MLP ----------------
__global__ void __launch_bounds__(128) final_kernel(const float* __restrict__ adj,
                                                    const float* __restrict__ gpre,
                                                    const float* __restrict__ W1,
                                                    const float* __restrict__ W2,
                                                    const float* __restrict__ b2,
                                                    float* __restrict__ out){
    extern __shared__ float sm[];
    float*  BvS = sm;                              // [j=128][k=128] pitch 129
    float*  A8  = sm + 128*129;                    // [8][128]
    float4* W3  = (float4*)(sm + 128*129 + 1024);
    int b = blockIdx.y, ic = blockIdx.x, tid = threadIdx.x;
    for (int r = 0; r < cN; r++)
        BvS[r*129 + tid] = g_Bv[((size_t)b*cN + r)*cH + tid];
    #pragma unroll
    for (int ii = 0; ii < 8; ii++)
        A8[ii*128 + tid] = g_A[((size_t)b*cN + ic*8 + ii)*cH + tid];
    W3[tid] = make_float4(W1[(2*cE)*cH + tid], W1[(2*cE + 1)*cH + tid], W2[tid], 0.f);
    float b2v = b2[0];
    __syncthreads();
    const float* brow = BvS + tid*129;
    #pragma unroll
    for (int ii = 0; ii < 8; ii++){
        int i = ic*8 + ii;
        size_t rbase = ((size_t)b*cN + i)*cN + tid;
        float adjv = adj[rbase], gv = gpre[rbase];
        const float* arow = A8 + ii*128;
        float acc = 0.f;
        #pragma unroll 4
        for (int k = 0; k < cH; k++){
            float4 ww = W3[k];
            float pre = arow[k] + brow[k] + adjv*ww.x + gv*ww.y;
            acc = fmaf(fmaxf(pre, 0.f), ww.z, acc);
        }
        out[rbase] = acc + b2v;
    }
}

// ---------------- launch ----------------
extern "C" void kernel_launch(void* const* d_in, const int* in_sizes, int n_in,
                              void* d_out, int out_size){
    const float* noisy_adj  = (const float*)d_in[0];
    const float* node_feats = (const float*)d_in[1];
    const float* feat_fnirs = (const float*)d_in[2];
    const float* feat_music = (const float*)d_in[3];
    const float* g_pre      = (const float*)d_in[4];
    const float* node_W     = (const float*)d_in[5];
    const float* node_b     = (const float*)d_in[6];
    const float* fnirs_W    = (const float*)d_in[7];
    const float* fnirs_b    = (const float*)d_in[8];
    const float* music_W    = (const float*)d_in[9];
    const float* music_b    = (const float*)d_in[10];
    const float* mlp_W1     = (const float*)d_in[11];
    const float* mlp_b1     = (const float*)d_in[12];
    const float* mlp_W2     = (const float*)d_in[13];
    const float* mlp_b2     = (const float*)d_in[14];
    const int*   t          = (const int*)d_in[15];

    float* out      = (float*)d_out;
    float* out_attn = out + cB*cN*cN;
    float* out_loss = out + cB*cN*cN + cB*cTf*cTm;

    cudaFuncSetAttribute(kv_kernel,    cudaFuncAttributeMaxDynamicSharedMemorySize, 131584);
    cudaFuncSetAttribute(attn_kernel,  cudaFuncAttributeMaxDynamicSharedMemorySize, ATTN_SMEM);
    cudaFuncSetAttribute(final_kernel, cudaFuncAttributeMaxDynamicSharedMemorySize, 72192);

    cudaMemsetAsync(out_attn, 0, (size_t)(cB*cTf*cTm + 1)*sizeof(float));

    kv_kernel<<<dim3(8, cB), 256, 131584>>>(feat_music, music_W, music_b);
    qpre_kernel<<<cB*cN, 128>>>(feat_fnirs, fnirs_W, fnirs_b, t);
    attn_kernel<<<cB*16, 256, ATTN_SMEM>>>(t, out_attn, out_loss);
    ab_kernel<<<cB*cN, 128>>>(node_feats, node_W, node_b, t, mlp_W1, mlp_b1);
    final_kernel<<<dim3(16, cB), 128, 72192>>>(noisy_adj, g_pre, mlp_W1, mlp_W2, mlp_b2, out);
}

// round 6
// speedup vs baseline: 2.5783x; 1.0824x over previous
#include <cuda_runtime.h>
#include <cuda_bf16.h>
#include <math.h>
#include <stdint.h>

#define cB 8
#define cN 128
#define cF 128
#define cTf 64
#define cTm 256
#define cDf 32
#define cDm 128
#define cE 64
#define cH 128
#define QSCALE 0.08838834764831843f

typedef unsigned long long ull;

// ---------------- device scratch ----------------
__device__ __align__(16) unsigned char g_kvB[cB*65536];     // per b: swizzled [m=256][h=128] bf16
__device__ __align__(16) unsigned char g_qA[cB*cN*16384];   // per n: swizzled [f=64][h=128] bf16 (q*scale)
__device__ float g_qt[cB*cN*cH];                            // q at t-row (fp32)
__device__ float g_cond[cB*cN*cH];                          // ctx at t-row
__device__ float g_A[cB*cN*cH];
__device__ float g_Bv[cB*cN*cH];

// ---------------- helpers ----------------
__device__ __forceinline__ uint32_t smem_u32(const void* p){
    uint32_t a;
    asm("{ .reg .u64 t; cvta.to.shared.u64 t, %1; cvt.u32.u64 %0, t; }" : "=r"(a) : "l"(p));
    return a;
}
__device__ __forceinline__ uint32_t tile_off(int r, int c, int atom_rows){
    uint32_t boff = (uint32_t)((r>>3) + (c>>6)*atom_rows)*1024u + (uint32_t)(r&7)*128u + (uint32_t)(c&63)*2u;
    return boff ^ ((boff >> 3) & 0x70u);
}
#define LDM_X4(r, a) \
    asm volatile("ldmatrix.sync.aligned.m8n8.x4.shared.b16 {%0,%1,%2,%3}, [%4];" \
        : "=r"((r)[0]),"=r"((r)[1]),"=r"((r)[2]),"=r"((r)[3]) : "r"(a))

__device__ __forceinline__ void mma_bf16(float* c, const uint32_t* a, uint32_t b0, uint32_t b1){
    asm volatile("mma.sync.aligned.m16n8k16.row.col.f32.bf16.bf16.f32 "
        "{%0,%1,%2,%3}, {%4,%5,%6,%7}, {%8,%9}, {%0,%1,%2,%3};"
        : "+f"(c[0]),"+f"(c[1]),"+f"(c[2]),"+f"(c[3])
        : "r"(a[0]),"r"(a[1]),"r"(a[2]),"r"(a[3]), "r"(b0),"r"(b1));
}

// fast exp on the FMA pipe: magic-number rint + degree-6 Taylor on |x|<=ln2/2
__device__ __forceinline__ float fexp(float v){
    float t = fmaf(v, 1.4426950408889634f, 12582912.0f);   // round-to-nearest int in mantissa
    int   j = __float_as_int(t) - 0x4B400000;
    float kf = t - 12582912.0f;
    float x = fmaf(kf, -0.6931471805599453f, v);
    float p = 1.3888889e-3f;
    p = fmaf(p, x, 8.3333333e-3f);
    p = fmaf(p, x, 4.1666667e-2f);
    p = fmaf(p, x, 1.6666667e-1f);
    p = fmaf(p, x, 0.5f);
    p = fmaf(p, x, 1.0f);
    p = fmaf(p, x, 1.0f);
    return p * __int_as_float((j + 127) << 23);
}

// packed f32x2
__device__ __forceinline__ ull pack2(float x){ ull r; asm("mov.b64 %0, {%1, %1};" : "=l"(r) : "f"(x)); return r; }
__device__ __forceinline__ ull packab(float a, float b){ ull r; asm("mov.b64 %0, {%1, %2};" : "=l"(r) : "f"(a), "f"(b)); return r; }
__device__ __forceinline__ void fma2(ull &acc, ull a, ull b){ asm("fma.rn.f32x2 %0, %1, %2, %0;" : "+l"(acc) : "l"(a), "l"(b)); }
__device__ __forceinline__ float2 u2f2(ull v){ float2 f; asm("mov.b64 {%0, %1}, %2;" : "=f"(f.x), "=f"(f.y) : "l"(v)); return f; }

// ---------------- kv -> bf16 swizzled tile ----------------
__global__ void __launch_bounds__(256) kv_kernel(const float* __restrict__ music,
                                                 const float* __restrict__ W,
                                                 const float* __restrict__ bias){
    extern __shared__ float sm[];            // musT [d=128][m=256] pitch 257 + sW [128d][16h]
    float* sW = sm + 128*257;
    int b  = blockIdx.y, hc = blockIdx.x, tid = threadIdx.x;
    for (int idx = tid; idx < cTm*cDm; idx += 256){
        int m = idx >> 7, d = idx & 127;
        sm[d*257 + m] = music[((size_t)b*cTm + m)*cDm + d];
    }
    for (int idx = tid; idx < 128*16; idx += 256){
        int d = idx >> 4, hh = idx & 15;
        sW[idx] = W[d*cH + hc*16 + hh];
    }
    __syncthreads();
    int m = tid;
    unsigned char* tb = g_kvB + (size_t)b*65536;
    for (int hh = 0; hh < 16; hh++){
        int h = hc*16 + hh;
        float acc = bias[h];
        #pragma unroll 8
        for (int d = 0; d < cDm; d++)
            acc = fmaf(sm[d*257 + m], sW[d*16 + hh], acc);
        *(__nv_bfloat16*)(tb + tile_off(m, h, 32)) = __float2bfloat16(acc);
    }
}

// ---------------- q -> bf16 scaled tile (per n) + t-row fp32 ----------------
__global__ void __launch_bounds__(128) qpre_kernel(const float* __restrict__ feat,
                                                   const float* __restrict__ W,
                                                   const float* __restrict__ bias,
                                                   const int* __restrict__ t){
    __shared__ float sfeat[cTf*cDf];
    int bn = blockIdx.x, tid = threadIdx.x;
    int b = bn >> 7;
    int trow = t[b]; trow = trow < 0 ? 0 : (trow > cTf-1 ? cTf-1 : trow);
    {
        const float4* fs = (const float4*)(feat + (size_t)bn*cTf*cDf);
        float4* fd = (float4*)sfeat;
        #pragma unroll
        for (int i = tid; i < 512; i += 128) fd[i] = fs[i];
    }
    float w[cDf];
    #pragma unroll
    for (int d = 0; d < cDf; d++) w[d] = W[d*cH + tid];
    float bs = bias[tid];
    __syncthreads();
    unsigned char* tb = g_qA + (size_t)bn*16384;
    for (int j = 0; j < 32; j++){
        ull acc = pack2(bs);
        const float* ra = sfeat + (2*j)*cDf;
        const float* rb = sfeat + (2*j+1)*cDf;
        #pragma unroll
        for (int d = 0; d < cDf; d++)
            fma2(acc, packab(ra[d], rb[d]), pack2(w[d]));
        float2 q2 = u2f2(acc);
        if (2*j   == trow) g_qt[(size_t)bn*cH + tid] = q2.x;
        if (2*j+1 == trow) g_qt[(size_t)bn*cH + tid] = q2.y;
        *(__nv_bfloat16*)(tb + tile_off(2*j,   tid, 8)) = __float2bfloat16(q2.x * QSCALE);
        *(__nv_bfloat16*)(tb + tile_off(2*j+1, tid, 8)) = __float2bfloat16(q2.y * QSCALE);
    }
}

// ---------------- attention (mma.sync bf16) ----------------
#define SM_B    0
#define SM_A    65536
#define SM_ZU   98304
#define SM_PROW 100352
#define SM_RED  108544
#define ATTN_SMEM 108800

__global__ void __launch_bounds__(256, 1) attn_kernel(const int* __restrict__ t,
                                                      float* __restrict__ out_attn,
                                                      float* __restrict__ out_loss){
    extern __shared__ char smem[];
    uint32_t sbase = smem_u32(smem);
    float2* zu    = (float2*)(smem + SM_ZU);    // [64 rows][4 wm]
    float*  prowS = (float*)(smem + SM_PROW);   // [8 n][256 m]
    float*  red   = (float*)(smem + SM_RED);

    int tid = threadIdx.x, wid = tid >> 5, lane = tid & 31;
    int b = blockIdx.x >> 4, nbase = (blockIdx.x & 15) * 8;
    int wf = wid >> 2, wm = wid & 3;            // warp grid 2 (f) x 4 (m)
    int f0 = wf*32, m0 = wm*64;
    int qr = lane >> 2, qc = lane & 3;

    {
        const float4* bs = (const float4*)(g_kvB + (size_t)b*65536);
        float4* bd = (float4*)(smem + SM_B);
        #pragma unroll
        for (int i = 0; i < 16; i++) bd[tid + i*256] = bs[tid + i*256];
        const float4* as = (const float4*)(g_qA + (size_t)(b*cN + nbase)*16384);
        float4* ad = (float4*)(smem + SM_A);
        #pragma unroll
        for (int i = 0; i < 4; i++) ad[tid + i*256] = as[tid + i*256];
    }
    __syncthreads();

    int trow = t[b]; trow = trow < 0 ? 0 : (trow > cTf-1 ? cTf-1 : trow);
    float entacc = 0.f;
    float accW[2][8][4];
    #pragma unroll
    for (int mt = 0; mt < 2; mt++)
        #pragma unroll
        for (int nt = 0; nt < 8; nt++)
            #pragma unroll
            for (int i = 0; i < 4; i++) accW[mt][nt][i] = 0.f;

    int arow = (lane & 15), acolk = (lane >> 4) * 8;
    int brow = ((lane >> 4) & 1) * 8 + (lane & 7), bcolk = ((lane >> 3) & 1) * 8;

    for (int np = 0; np < 8; np++){
        __syncthreads();
        if (np < 7){
            const float4* as = (const float4*)(g_qA + (size_t)(b*cN + nbase + np + 1)*16384);
            float4* ad = (float4*)(smem + SM_A + ((np+1)&1)*16384);
            #pragma unroll
            for (int i = 0; i < 4; i++) ad[tid + i*256] = as[tid + i*256];
        }
        uint32_t smA = sbase + SM_A + (np&1)*16384;
        uint32_t smB = sbase + SM_B;

        float C[2][8][4];
        #pragma unroll
        for (int mt = 0; mt < 2; mt++)
            #pragma unroll
            for (int nt = 0; nt < 8; nt++)
                #pragma unroll
                for (int i = 0; i < 4; i++) C[mt][nt][i] = 0.f;

        #pragma unroll
        for (int kk = 0; kk < 8; kk++){
            int k0 = kk*16;
            uint32_t a0[4], a1[4], bb[4][4];
            LDM_X4(a0, smA + tile_off(f0 + arow,      k0 + acolk, 8));
            LDM_X4(a1, smA + tile_off(f0 + 16 + arow, k0 + acolk, 8));
            #pragma unroll
            for (int nt2 = 0; nt2 < 4; nt2++)
                LDM_X4(bb[nt2], smB + tile_off(m0 + nt2*16 + brow, k0 + bcolk, 32));
            #pragma unroll
            for (int nt = 0; nt < 8; nt++){
                uint32_t b0 = bb[nt>>1][(nt&1)*2], b1 = bb[nt>>1][(nt&1)*2 + 1];
                mma_bf16(C[0][nt], a0, b0, b1);
                mma_bf16(C[1][nt], a1, b0, b1);
            }
        }

        // ---- epilogue on fragments ----
        #pragma unroll
        for (int g = 0; g < 4; g++){
            int mt = g >> 1, pr = g & 1;
            float Z = 0.f, U = 0.f;
            #pragma unroll
            for (int nt = 0; nt < 8; nt++){
                #pragma unroll
                for (int c = 0; c < 2; c++){
                    float v = C[mt][nt][pr*2 + c];
                    float e = fexp(v);
                    Z += e; U = fmaf(e, v, U);
                    C[mt][nt][pr*2 + c] = e;
                }
            }
            #pragma unroll
            for (int o = 1; o <= 2; o <<= 1){
                Z += __shfl_xor_sync(0xffffffffu, Z, o);
                U += __shfl_xor_sync(0xffffffffu, U, o);
            }
            if (qc == 0){
                int f = f0 + mt*16 + qr + 8*pr;
                zu[f*4 + wm] = make_float2(Z, U);
            }
        }
        __syncthreads();
        #pragma unroll
        for (int g = 0; g < 4; g++){
            int mt = g >> 1, pr = g & 1;
            int f = f0 + mt*16 + qr + 8*pr;
            float2 z0 = zu[f*4+0], z1 = zu[f*4+1], z2 = zu[f*4+2], z3 = zu[f*4+3];
            float Zt = z0.x + z1.x + z2.x + z3.x;
            float Ut = z0.y + z1.y + z2.y + z3.y;
            float inv = __fdividef(1.f, Zt);
            if (wm == 0 && qc == 0) entacc += __logf(Zt) - Ut*inv;
            bool isT = (f == trow);
            #pragma unroll
            for (int nt = 0; nt < 8; nt++){
                #pragma unroll
                for (int c = 0; c < 2; c++){
                    float p = C[mt][nt][pr*2 + c] * inv;
                    accW[mt][nt][pr*2 + c] += p;
                    if (isT) prowS[np*256 + m0 + nt*8 + 2*qc + c] = p;
                }
            }
        }
    }
    __syncthreads();

    // ---- ctx for the 8 t-rows from bf16 kv tile ----
    {
        int g = tid >> 7, h = tid & 127;
        uint32_t hbase = (uint32_t)(h >> 6)*32768u;
        uint32_t hlow  = (uint32_t)((h & 63)*2);
        uint32_t offj[8];
        #pragma unroll
        for (int j = 0; j < 8; j++) offj[j] = (uint32_t)(j*128) + (hlow ^ (uint32_t)(j<<4));
        float c0=0.f, c1=0.f, c2=0.f, c3=0.f;
        const float* pr = prowS + g*4*256;
        for (int mg = 0; mg < 32; mg++){
            uint32_t abase = hbase + (uint32_t)mg*1024u;
            #pragma unroll
            for (int j = 0; j < 8; j++){
                unsigned short u = *(const unsigned short*)(smem + SM_B + abase + offj[j]);
                float kvv = __bfloat162float(*reinterpret_cast<__nv_bfloat16*>(&u));
                int m = mg*8 + j;
                c0 = fmaf(pr[m],       kvv, c0);
                c1 = fmaf(pr[256 + m], kvv, c1);
                c2 = fmaf(pr[512 + m], kvv, c2);
                c3 = fmaf(pr[768 + m], kvv, c3);
            }
        }
        size_t cb = ((size_t)b*cN + nbase + 4*g)*cH + h;
        g_cond[cb]        = c0;
        g_cond[cb + cH]   = c1;
        g_cond[cb + 2*cH] = c2;
        g_cond[cb + 3*cH] = c3;
    }

    #pragma unroll
    for (int o = 16; o > 0; o >>= 1) entacc += __shfl_xor_sync(0xffffffffu, entacc, o);
    if (lane == 0) red[wid] = entacc;
    __syncthreads();
    if (tid == 0){
        float tot = 0.f;
        #pragma unroll
        for (int i = 0; i < 8; i++) tot += red[i];
        atomicAdd(out_loss, tot * (1.f/(float)(cB*cN*cTf)));
    }

    #pragma unroll
    for (int mt = 0; mt < 2; mt++)
        #pragma unroll
        for (int nt = 0; nt < 8; nt++)
            #pragma unroll
            for (int i = 0; i < 4; i++){
                int f = f0 + mt*16 + qr + 8*(i>>1);
                int m = m0 + nt*8 + 2*qc + (i&1);
                atomicAdd(out_attn + ((size_t)b*cTf + f)*cTm + m, accW[mt][nt][i] * (1.f/128.f));
            }
}

// ---------------- ab: W1 staged in smem, 8 n per block in registers ----------------
#define OF_W1A 0
#define OF_W1B 8192
#define OF_W1C 16384
#define OF_WN  32768
#define OF_NF  40960
#define OF_HT  41984
#define OF_CT  42496
#define OF_TEW 43520
#define OF_TES 43648
#define AB_SMEM ((43648 + 64) * 4)

__global__ void __launch_bounds__(128) ab_kernel(const float* __restrict__ nf,
                                                 const float* __restrict__ Wn,
                                                 const float* __restrict__ bn,
                                                 const int* __restrict__ t,
                                                 const float* __restrict__ W1,
                                                 const float* __restrict__ b1){
    extern __shared__ float sm[];
    int tid = threadIdx.x;
    int b = blockIdx.x >> 4, n0 = (blockIdx.x & 15) * 8;
    int bn0 = b*cN + n0;

    // stage W1 rows 0..127 (hi|hj), rows 130..257 (cond), Wn, nf(8 rows), tes
    {
        const float4* s1 = (const float4*)W1;
        float4* d1 = (float4*)(sm + OF_W1A);
        for (int i = tid; i < 4096; i += 128) d1[i] = s1[i];
        const float4* s2 = (const float4*)(W1 + 130*cH);
        float4* d2 = (float4*)(sm + OF_W1C);
        for (int i = tid; i < 4096; i += 128) d2[i] = s2[i];
        const float4* s3 = (const float4*)Wn;
        float4* d3 = (float4*)(sm + OF_WN);
        for (int i = tid; i < 2048; i += 128) d3[i] = s3[i];
        const float4* s4 = (const float4*)(nf + (size_t)bn0*cF);
        float4* d4 = (float4*)(sm + OF_NF);
        for (int i = tid; i < 256; i += 128) d4[i] = s4[i];
        if (tid < 32){
            int ti = t[b]; ti = ti < 0 ? 0 : (ti > cTf-1 ? cTf-1 : ti);
            float invf = expf(-(float)tid * (logf(10000.0f) / 31.0f));
            float fr = (float)ti * invf;
            sm[OF_TES + tid]      = sinf(fr);
            sm[OF_TES + tid + 32] = cosf(fr);
        }
        // condT[c][n]
        #pragma unroll
        for (int n = 0; n < 8; n++){
            size_t idx = (size_t)(bn0 + n)*cH + tid;
            sm[OF_CT + tid*8 + n] = g_qt[idx] + g_cond[idx];
        }
    }
    __syncthreads();

    // h: thread -> (e = tid&63, ng = tid>>6), 4 n each; write transposed [e][n]
    {
        int e = tid & 63, ng = tid >> 6;
        float acc0 = bn[e], acc1 = acc0, acc2 = acc0, acc3 = acc0;
        const float* f0 = sm + OF_NF + (ng*4+0)*cF;
        const float* f1 = sm + OF_NF + (ng*4+1)*cF;
        const float* f2 = sm + OF_NF + (ng*4+2)*cF;
        const float* f3 = sm + OF_NF + (ng*4+3)*cF;
        #pragma unroll 8
        for (int f = 0; f < cF; f++){
            float w = sm[OF_WN + f*cE + e];
            acc0 = fmaf(f0[f], w, acc0);
            acc1 = fmaf(f1[f], w, acc1);
            acc2 = fmaf(f2[f], w, acc2);
            acc3 = fmaf(f3[f], w, acc3);
        }
        sm[OF_HT + e*8 + ng*4 + 0] = acc0;
        sm[OF_HT + e*8 + ng*4 + 1] = acc1;
        sm[OF_HT + e*8 + ng*4 + 2] = acc2;
        sm[OF_HT + e*8 + ng*4 + 3] = acc3;
    }
    // TEW[k] = b1[k] + tes @ W1_time (needs tes: same sync covers h write below)
    __syncthreads();
    {
        int k = tid;
        float acc = b1[k];
        #pragma unroll 8
        for (int e = 0; e < 64; e++)
            acc = fmaf(sm[OF_TES + e], W1[(258 + e)*cH + k], acc);
        sm[OF_TEW + k] = acc;
    }
    __syncthreads();

    // main: thread = k; 8 n in registers
    {
        int k = tid;
        float tw = sm[OF_TEW + k];
        float a[8], bv[8];
        #pragma unroll
        for (int n = 0; n < 8; n++){ a[n] = 0.f; bv[n] = tw; }
        #pragma unroll 4
        for (int e = 0; e < cE; e++){
            float wa = sm[OF_W1A + e*cH + k];
            float wb = sm[OF_W1B + e*cH + k];
            float4 h0 = *(const float4*)(sm + OF_HT + e*8);
            float4 h1 = *(const float4*)(sm + OF_HT + e*8 + 4);
            a[0] = fmaf(h0.x, wa, a[0]); bv[0] = fmaf(h0.x, wb, bv[0]);
            a[1] = fmaf(h0.y, wa, a[1]); bv[1] = fmaf(h0.y, wb, bv[1]);
            a[2] = fmaf(h0.z, wa, a[2]); bv[2] = fmaf(h0.z, wb, bv[2]);
            a[3] = fmaf(h0.w, wa, a[3]); bv[3] = fmaf(h0.w, wb, bv[3]);
            a[4] = fmaf(h1.x, wa, a[4]); bv[4] = fmaf(h1.x, wb, bv[4]);
            a[5] = fmaf(h1.y, wa, a[5]); bv[5] = fmaf(h1.y, wb, bv[5]);
            a[6] = fmaf(h1.z, wa, a[6]); bv[6] = fmaf(h1.z, wb, bv[6]);
            a[7] = fmaf(h1.w, wa, a[7]); bv[7] = fmaf(h1.w, wb, bv[7]);
        }
        #pragma unroll 4
        for (int c = 0; c < cH; c++){
            float wc = sm[OF_W1C + c*cH + k];
            float4 c0 = *(const float4*)(sm + OF_CT + c*8);
            float4 c1 = *(const float4*)(sm + OF_CT + c*8 + 4);
            bv[0] = fmaf(c0.x, wc, bv[0]);
            bv[1] = fmaf(c0.y, wc, bv[1]);
            bv[2] = fmaf(c0.z, wc, bv[2]);
            bv[3] = fmaf(c0.w, wc, bv[3]);
            bv[4] = fmaf(c1.x, wc, bv[4]);
            bv[5] = fmaf(c1.y, wc, bv[5]);
            bv[6] = fmaf(c1.z, wc, bv[6]);
            bv[7] = fmaf(c1.w, wc, bv[7]);
        }
        #pragma unroll
        for (int n = 0; n < 8; n++){
            g_A[(size_t)(bn0 + n)*cH + k]  = a[n];
            g_Bv[(size_t)(bn0 + n)*cH + k] = bv[n];
        }
    }
}

// ---------------- final edge MLP ----------------
__global__ void __launch_bounds__(128) final_kernel(const float* __restrict__ adj,
                                                    const float* __restrict__ gpre,
                                                    const float* __restrict__ W1,
                                                    const float* __restrict__ W2,
                                                    const float* __restrict__ b2,
                                                    float* __restrict__ out){
    extern __shared__ float sm[];
    float*  BvS = sm;                              // [j=128][k=128] pitch 129
    float*  A8  = sm + 128*129;                    // [8][128]
    float4* W3  = (float4*)(sm + 128*129 + 1024);
    int b = blockIdx.y, ic = blockIdx.x, tid = threadIdx.x;
    for (int r = 0; r < cN; r++)
        BvS[r*129 + tid] = g_Bv[((size_t)b*cN + r)*cH + tid];
    #pragma unroll
    for (int ii = 0; ii < 8; ii++)
        A8[ii*128 + tid] = g_A[((size_t)b*cN + ic*8 + ii)*cH + tid];
    W3[tid] = make_float4(W1[(2*cE)*cH + tid], W1[(2*cE + 1)*cH + tid], W2[tid], 0.f);
    float b2v = b2[0];
    __syncthreads();
    const float* brow = BvS + tid*129;
    #pragma unroll
    for (int ii = 0; ii < 8; ii++){
        int i = ic*8 + ii;
        size_t rbase = ((size_t)b*cN + i)*cN + tid;
        float adjv = adj[rbase], gv = gpre[rbase];
        const float* arow = A8 + ii*128;
        float acc = 0.f;
        #pragma unroll 4
        for (int k = 0; k < cH; k++){
            float4 ww = W3[k];
            float pre = arow[k] + brow[k] + adjv*ww.x + gv*ww.y;
            acc = fmaf(fmaxf(pre, 0.f), ww.z, acc);
        }
        out[rbase] = acc + b2v;
    }
}

// ---------------- launch ----------------
extern "C" void kernel_launch(void* const* d_in, const int* in_sizes, int n_in,
                              void* d_out, int out_size){
    const float* noisy_adj  = (const float*)d_in[0];
    const float* node_feats = (const float*)d_in[1];
    const float* feat_fnirs = (const float*)d_in[2];
    const float* feat_music = (const float*)d_in[3];
    const float* g_pre      = (const float*)d_in[4];
    const float* node_W     = (const float*)d_in[5];
    const float* node_b     = (const float*)d_in[6];
    const float* fnirs_W    = (const float*)d_in[7];
    const float* fnirs_b    = (const float*)d_in[8];
    const float* music_W    = (const float*)d_in[9];
    const float* music_b    = (const float*)d_in[10];
    const float* mlp_W1     = (const float*)d_in[11];
    const float* mlp_b1     = (const float*)d_in[12];
    const float* mlp_W2     = (const float*)d_in[13];
    const float* mlp_b2     = (const float*)d_in[14];
    const int*   t          = (const int*)d_in[15];

    float* out      = (float*)d_out;
    float* out_attn = out + cB*cN*cN;
    float* out_loss = out + cB*cN*cN + cB*cTf*cTm;

    cudaFuncSetAttribute(kv_kernel,    cudaFuncAttributeMaxDynamicSharedMemorySize, 139776);
    cudaFuncSetAttribute(attn_kernel,  cudaFuncAttributeMaxDynamicSharedMemorySize, ATTN_SMEM);
    cudaFuncSetAttribute(ab_kernel,    cudaFuncAttributeMaxDynamicSharedMemorySize, AB_SMEM);
    cudaFuncSetAttribute(final_kernel, cudaFuncAttributeMaxDynamicSharedMemorySize, 72192);

    cudaMemsetAsync(out_attn, 0, (size_t)(cB*cTf*cTm + 1)*sizeof(float));

    kv_kernel<<<dim3(8, cB), 256, 139776>>>(feat_music, music_W, music_b);
    qpre_kernel<<<cB*cN, 128>>>(feat_fnirs, fnirs_W, fnirs_b, t);
    attn_kernel<<<cB*16, 256, ATTN_SMEM>>>(t, out_attn, out_loss);
    ab_kernel<<<cB*16, 128, AB_SMEM>>>(node_feats, node_W, node_b, t, mlp_W1, mlp_b1);
    final_kernel<<<dim3(16, cB), 128, 72192>>>(noisy_adj, g_pre, mlp_W1, mlp_W2, mlp_b2, out);
}

// round 7
// speedup vs baseline: 2.7156x; 1.0532x over previous
#include <cuda_runtime.h>
#include <cuda_bf16.h>
#include <math.h>
#include <stdint.h>

#define cB 8
#define cN 128
#define cF 128
#define cTf 64
#define cTm 256
#define cDf 32
#define cDm 128
#define cE 64
#define cH 128
#define QSCALE 0.08838834764831843f

typedef unsigned long long ull;

// ---------------- device scratch ----------------
__device__ __align__(16) unsigned char g_kvB[cB*65536];     // per b: swizzled [m=256][h=128] bf16
__device__ __align__(16) unsigned char g_qA[cB*cN*16384];   // per n: swizzled [f=64][h=128] bf16 (q*scale)
__device__ float g_qt[cB*cN*cH];                            // q at t-row (fp32)
__device__ float g_cond[cB*cN*cH];                          // ctx at t-row
__device__ float g_A[cB*cN*cH];
__device__ float g_Bv[cB*cN*cH];

// ---------------- helpers ----------------
__device__ __forceinline__ uint32_t smem_u32(const void* p){
    uint32_t a;
    asm("{ .reg .u64 t; cvta.to.shared.u64 t, %1; cvt.u32.u64 %0, t; }" : "=r"(a) : "l"(p));
    return a;
}
__device__ __forceinline__ uint32_t tile_off(int r, int c, int atom_rows){
    uint32_t boff = (uint32_t)((r>>3) + (c>>6)*atom_rows)*1024u + (uint32_t)(r&7)*128u + (uint32_t)(c&63)*2u;
    return boff ^ ((boff >> 3) & 0x70u);
}
#define LDM_X4(r, a) \
    asm volatile("ldmatrix.sync.aligned.m8n8.x4.shared.b16 {%0,%1,%2,%3}, [%4];" \
        : "=r"((r)[0]),"=r"((r)[1]),"=r"((r)[2]),"=r"((r)[3]) : "r"(a))

__device__ __forceinline__ void mma_bf16(float* c, const uint32_t* a, uint32_t b0, uint32_t b1){
    asm volatile("mma.sync.aligned.m16n8k16.row.col.f32.bf16.bf16.f32 "
        "{%0,%1,%2,%3}, {%4,%5,%6,%7}, {%8,%9}, {%0,%1,%2,%3};"
        : "+f"(c[0]),"+f"(c[1]),"+f"(c[2]),"+f"(c[3])
        : "r"(a[0]),"r"(a[1]),"r"(a[2]),"r"(a[3]), "r"(b0),"r"(b1));
}

// fast exp on the FMA pipe
__device__ __forceinline__ float fexp(float v){
    float t = fmaf(v, 1.4426950408889634f, 12582912.0f);
    int   j = __float_as_int(t) - 0x4B400000;
    float kf = t - 12582912.0f;
    float x = fmaf(kf, -0.6931471805599453f, v);
    float p = 1.3888889e-3f;
    p = fmaf(p, x, 8.3333333e-3f);
    p = fmaf(p, x, 4.1666667e-2f);
    p = fmaf(p, x, 1.6666667e-1f);
    p = fmaf(p, x, 0.5f);
    p = fmaf(p, x, 1.0f);
    p = fmaf(p, x, 1.0f);
    return p * __int_as_float((j + 127) << 23);
}

// packed f32x2
__device__ __forceinline__ ull pack2(float x){ ull r; asm("mov.b64 %0, {%1, %1};" : "=l"(r) : "f"(x)); return r; }
__device__ __forceinline__ ull packab(float a, float b){ ull r; asm("mov.b64 %0, {%1, %2};" : "=l"(r) : "f"(a), "f"(b)); return r; }
__device__ __forceinline__ void fma2(ull &acc, ull a, ull b){ asm("fma.rn.f32x2 %0, %1, %2, %0;" : "+l"(acc) : "l"(a), "l"(b)); }
__device__ __forceinline__ float2 u2f2(ull v){ float2 f; asm("mov.b64 {%0, %1}, %2;" : "=f"(f.x), "=f"(f.y) : "l"(v)); return f; }

// ---------------- kv -> bf16 swizzled tile ----------------
__global__ void __launch_bounds__(256) kv_kernel(const float* __restrict__ music,
                                                 const float* __restrict__ W,
                                                 const float* __restrict__ bias){
    extern __shared__ float sm[];            // musT [d=128][m=256] pitch 257 + sW [128d][16h]
    float* sW = sm + 128*257;
    int b  = blockIdx.y, hc = blockIdx.x, tid = threadIdx.x;
    for (int idx = tid; idx < cTm*cDm; idx += 256){
        int m = idx >> 7, d = idx & 127;
        sm[d*257 + m] = music[((size_t)b*cTm + m)*cDm + d];
    }
    for (int idx = tid; idx < 128*16; idx += 256){
        int d = idx >> 4, hh = idx & 15;
        sW[idx] = W[d*cH + hc*16 + hh];
    }
    __syncthreads();
    int m = tid;
    unsigned char* tb = g_kvB + (size_t)b*65536;
    for (int hh = 0; hh < 16; hh++){
        int h = hc*16 + hh;
        float acc = bias[h];
        #pragma unroll 8
        for (int d = 0; d < cDm; d++)
            acc = fmaf(sm[d*257 + m], sW[d*16 + hh], acc);
        *(__nv_bfloat16*)(tb + tile_off(m, h, 32)) = __float2bfloat16(acc);
    }
}

// ---------------- q -> bf16 scaled tile (per n) + t-row fp32 ----------------
__global__ void __launch_bounds__(128) qpre_kernel(const float* __restrict__ feat,
                                                   const float* __restrict__ W,
                                                   const float* __restrict__ bias,
                                                   const int* __restrict__ t){
    __shared__ float sfeat[cTf*cDf];
    int bn = blockIdx.x, tid = threadIdx.x;
    int b = bn >> 7;
    int trow = t[b]; trow = trow < 0 ? 0 : (trow > cTf-1 ? cTf-1 : trow);
    {
        const float4* fs = (const float4*)(feat + (size_t)bn*cTf*cDf);
        float4* fd = (float4*)sfeat;
        #pragma unroll
        for (int i = tid; i < 512; i += 128) fd[i] = fs[i];
    }
    float w[cDf];
    #pragma unroll
    for (int d = 0; d < cDf; d++) w[d] = W[d*cH + tid];
    float bs = bias[tid];
    __syncthreads();
    unsigned char* tb = g_qA + (size_t)bn*16384;
    for (int j = 0; j < 32; j++){
        ull acc = pack2(bs);
        const float* ra = sfeat + (2*j)*cDf;
        const float* rb = sfeat + (2*j+1)*cDf;
        #pragma unroll
        for (int d = 0; d < cDf; d++)
            fma2(acc, packab(ra[d], rb[d]), pack2(w[d]));
        float2 q2 = u2f2(acc);
        if (2*j   == trow) g_qt[(size_t)bn*cH + tid] = q2.x;
        if (2*j+1 == trow) g_qt[(size_t)bn*cH + tid] = q2.y;
        *(__nv_bfloat16*)(tb + tile_off(2*j,   tid, 8)) = __float2bfloat16(q2.x * QSCALE);
        *(__nv_bfloat16*)(tb + tile_off(2*j+1, tid, 8)) = __float2bfloat16(q2.y * QSCALE);
    }
}

// ---------------- attention (mma.sync bf16) ----------------
#define SM_B    0
#define SM_A    65536
#define SM_ZU   98304
#define SM_PROW 100352
#define SM_RED  108544
#define ATTN_SMEM 108800

__global__ void __launch_bounds__(256, 1) attn_kernel(const int* __restrict__ t,
                                                      float* __restrict__ out_attn,
                                                      float* __restrict__ out_loss){
    extern __shared__ char smem[];
    uint32_t sbase = smem_u32(smem);
    float2* zu    = (float2*)(smem + SM_ZU);
    float*  prowS = (float*)(smem + SM_PROW);
    float*  red   = (float*)(smem + SM_RED);

    int tid = threadIdx.x, wid = tid >> 5, lane = tid & 31;
    int b = blockIdx.x >> 4, nbase = (blockIdx.x & 15) * 8;
    int wf = wid >> 2, wm = wid & 3;
    int f0 = wf*32, m0 = wm*64;
    int qr = lane >> 2, qc = lane & 3;

    {
        const float4* bs = (const float4*)(g_kvB + (size_t)b*65536);
        float4* bd = (float4*)(smem + SM_B);
        #pragma unroll
        for (int i = 0; i < 16; i++) bd[tid + i*256] = bs[tid + i*256];
        const float4* as = (const float4*)(g_qA + (size_t)(b*cN + nbase)*16384);
        float4* ad = (float4*)(smem + SM_A);
        #pragma unroll
        for (int i = 0; i < 4; i++) ad[tid + i*256] = as[tid + i*256];
    }
    __syncthreads();

    int trow = t[b]; trow = trow < 0 ? 0 : (trow > cTf-1 ? cTf-1 : trow);
    float entacc = 0.f;
    float accW[2][8][4];
    #pragma unroll
    for (int mt = 0; mt < 2; mt++)
        #pragma unroll
        for (int nt = 0; nt < 8; nt++)
            #pragma unroll
            for (int i = 0; i < 4; i++) accW[mt][nt][i] = 0.f;

    int arow = (lane & 15), acolk = (lane >> 4) * 8;
    int brow = ((lane >> 4) & 1) * 8 + (lane & 7), bcolk = ((lane >> 3) & 1) * 8;

    for (int np = 0; np < 8; np++){
        __syncthreads();
        if (np < 7){
            const float4* as = (const float4*)(g_qA + (size_t)(b*cN + nbase + np + 1)*16384);
            float4* ad = (float4*)(smem + SM_A + ((np+1)&1)*16384);
            #pragma unroll
            for (int i = 0; i < 4; i++) ad[tid + i*256] = as[tid + i*256];
        }
        uint32_t smA = sbase + SM_A + (np&1)*16384;
        uint32_t smB = sbase + SM_B;

        float C[2][8][4];
        #pragma unroll
        for (int mt = 0; mt < 2; mt++)
            #pragma unroll
            for (int nt = 0; nt < 8; nt++)
                #pragma unroll
                for (int i = 0; i < 4; i++) C[mt][nt][i] = 0.f;

        #pragma unroll
        for (int kk = 0; kk < 8; kk++){
            int k0 = kk*16;
            uint32_t a0[4], a1[4], bb[4][4];
            LDM_X4(a0, smA + tile_off(f0 + arow,      k0 + acolk, 8));
            LDM_X4(a1, smA + tile_off(f0 + 16 + arow, k0 + acolk, 8));
            #pragma unroll
            for (int nt2 = 0; nt2 < 4; nt2++)
                LDM_X4(bb[nt2], smB + tile_off(m0 + nt2*16 + brow, k0 + bcolk, 32));
            #pragma unroll
            for (int nt = 0; nt < 8; nt++){
                uint32_t b0 = bb[nt>>1][(nt&1)*2], b1 = bb[nt>>1][(nt&1)*2 + 1];
                mma_bf16(C[0][nt], a0, b0, b1);
                mma_bf16(C[1][nt], a1, b0, b1);
            }
        }

        #pragma unroll
        for (int g = 0; g < 4; g++){
            int mt = g >> 1, pr = g & 1;
            float Z = 0.f, U = 0.f;
            #pragma unroll
            for (int nt = 0; nt < 8; nt++){
                #pragma unroll
                for (int c = 0; c < 2; c++){
                    float v = C[mt][nt][pr*2 + c];
                    float e = fexp(v);
                    Z += e; U = fmaf(e, v, U);
                    C[mt][nt][pr*2 + c] = e;
                }
            }
            #pragma unroll
            for (int o = 1; o <= 2; o <<= 1){
                Z += __shfl_xor_sync(0xffffffffu, Z, o);
                U += __shfl_xor_sync(0xffffffffu, U, o);
            }
            if (qc == 0){
                int f = f0 + mt*16 + qr + 8*pr;
                zu[f*4 + wm] = make_float2(Z, U);
            }
        }
        __syncthreads();
        #pragma unroll
        for (int g = 0; g < 4; g++){
            int mt = g >> 1, pr = g & 1;
            int f = f0 + mt*16 + qr + 8*pr;
            float2 z0 = zu[f*4+0], z1 = zu[f*4+1], z2 = zu[f*4+2], z3 = zu[f*4+3];
            float Zt = z0.x + z1.x + z2.x + z3.x;
            float Ut = z0.y + z1.y + z2.y + z3.y;
            float inv = __fdividef(1.f, Zt);
            if (wm == 0 && qc == 0) entacc += __logf(Zt) - Ut*inv;
            bool isT = (f == trow);
            #pragma unroll
            for (int nt = 0; nt < 8; nt++){
                #pragma unroll
                for (int c = 0; c < 2; c++){
                    float p = C[mt][nt][pr*2 + c] * inv;
                    accW[mt][nt][pr*2 + c] += p;
                    if (isT) prowS[np*256 + m0 + nt*8 + 2*qc + c] = p;
                }
            }
        }
    }
    __syncthreads();

    // ctx for the 8 t-rows
    {
        int g = tid >> 7, h = tid & 127;
        uint32_t hbase = (uint32_t)(h >> 6)*32768u;
        uint32_t hlow  = (uint32_t)((h & 63)*2);
        uint32_t offj[8];
        #pragma unroll
        for (int j = 0; j < 8; j++) offj[j] = (uint32_t)(j*128) + (hlow ^ (uint32_t)(j<<4));
        float c0=0.f, c1=0.f, c2=0.f, c3=0.f;
        const float* pr = prowS + g*4*256;
        for (int mg = 0; mg < 32; mg++){
            uint32_t abase = hbase + (uint32_t)mg*1024u;
            #pragma unroll
            for (int j = 0; j < 8; j++){
                unsigned short u = *(const unsigned short*)(smem + SM_B + abase + offj[j]);
                float kvv = __bfloat162float(*reinterpret_cast<__nv_bfloat16*>(&u));
                int m = mg*8 + j;
                c0 = fmaf(pr[m],       kvv, c0);
                c1 = fmaf(pr[256 + m], kvv, c1);
                c2 = fmaf(pr[512 + m], kvv, c2);
                c3 = fmaf(pr[768 + m], kvv, c3);
            }
        }
        size_t cb = ((size_t)b*cN + nbase + 4*g)*cH + h;
        g_cond[cb]        = c0;
        g_cond[cb + cH]   = c1;
        g_cond[cb + 2*cH] = c2;
        g_cond[cb + 3*cH] = c3;
    }

    #pragma unroll
    for (int o = 16; o > 0; o >>= 1) entacc += __shfl_xor_sync(0xffffffffu, entacc, o);
    if (lane == 0) red[wid] = entacc;
    __syncthreads();
    if (tid == 0){
        float tot = 0.f;
        #pragma unroll
        for (int i = 0; i < 8; i++) tot += red[i];
        atomicAdd(out_loss, tot * (1.f/(float)(cB*cN*cTf)));
    }

    #pragma unroll
    for (int mt = 0; mt < 2; mt++)
        #pragma unroll
        for (int nt = 0; nt < 8; nt++)
            #pragma unroll
            for (int i = 0; i < 4; i++){
                int f = f0 + mt*16 + qr + 8*(i>>1);
                int m = m0 + nt*8 + 2*qc + (i&1);
                atomicAdd(out_attn + ((size_t)b*cTf + f)*cTm + m, accW[mt][nt][i] * (1.f/128.f));
            }
}

// ---------------- ab: 512 threads, W1 in smem, (k, 2n) per thread ----------------
#define OF_W1A 0
#define OF_W1B 8192
#define OF_W1C 16384
#define OF_WN  32768
#define OF_NF  40960
#define OF_HT  41984
#define OF_CT  42496
#define OF_TEW 43520
#define OF_TES 43648
#define AB_SMEM ((43648 + 64) * 4)

__global__ void __launch_bounds__(512) ab_kernel(const float* __restrict__ nf,
                                                 const float* __restrict__ Wn,
                                                 const float* __restrict__ bn,
                                                 const int* __restrict__ t,
                                                 const float* __restrict__ W1,
                                                 const float* __restrict__ b1){
    extern __shared__ float sm[];
    int tid = threadIdx.x;
    int b = blockIdx.x >> 4, n0 = (blockIdx.x & 15) * 8;
    int bn0 = b*cN + n0;

    // stage W1 rows 0..127 (hi|hj), rows 130..257 (cond), Wn, nf(8 rows), tes, condT
    {
        const float4* s1 = (const float4*)W1;
        float4* d1 = (float4*)(sm + OF_W1A);
        for (int i = tid; i < 4096; i += 512) d1[i] = s1[i];
        const float4* s2 = (const float4*)(W1 + 130*cH);
        float4* d2 = (float4*)(sm + OF_W1C);
        for (int i = tid; i < 4096; i += 512) d2[i] = s2[i];
        const float4* s3 = (const float4*)Wn;
        float4* d3 = (float4*)(sm + OF_WN);
        for (int i = tid; i < 2048; i += 512) d3[i] = s3[i];
        const float4* s4 = (const float4*)(nf + (size_t)bn0*cF);
        float4* d4 = (float4*)(sm + OF_NF);
        for (int i = tid; i < 256; i += 512) d4[i] = s4[i];
        if (tid < 32){
            int ti = t[b]; ti = ti < 0 ? 0 : (ti > cTf-1 ? cTf-1 : ti);
            float invf = expf(-(float)tid * (logf(10000.0f) / 31.0f));
            float fr = (float)ti * invf;
            sm[OF_TES + tid]      = sinf(fr);
            sm[OF_TES + tid + 32] = cosf(fr);
        }
        // condT[c][n]: 512 threads -> (c = tid&127, two n per thread)
        {
            int c = tid & 127, ng = tid >> 7;
            size_t i0 = (size_t)(bn0 + 2*ng)*cH + c;
            sm[OF_CT + c*8 + 2*ng]     = g_qt[i0] + g_cond[i0];
            sm[OF_CT + c*8 + 2*ng + 1] = g_qt[i0 + cH] + g_cond[i0 + cH];
        }
    }
    __syncthreads();

    // h: 512 threads = (e = tid&63, n = tid>>6); write transposed [e][n]
    {
        int e = tid & 63, n = tid >> 6;
        float acc = bn[e];
        const float* fr = sm + OF_NF + n*cF;
        #pragma unroll 16
        for (int f = 0; f < cF; f++)
            acc = fmaf(fr[f], sm[OF_WN + f*cE + e], acc);
        sm[OF_HT + e*8 + n] = acc;
    }
    __syncthreads();
    // TEW[k]
    if (tid < 128){
        int k = tid;
        float acc = b1[k];
        #pragma unroll 8
        for (int e = 0; e < 64; e++)
            acc = fmaf(sm[OF_TES + e], W1[(258 + e)*cH + k], acc);
        sm[OF_TEW + k] = acc;
    }
    __syncthreads();

    // main: thread = (k = tid&127, g = tid>>7), each g owns n = {2g, 2g+1}
    {
        int k = tid & 127, g = tid >> 7;
        float tw = sm[OF_TEW + k];
        float a0 = 0.f, a1 = 0.f, bv0 = tw, bv1 = tw;
        const float2* hrow = (const float2*)(sm + OF_HT) + g;      // stride 4 float2
        const float2* crow = (const float2*)(sm + OF_CT) + g;
        #pragma unroll 8
        for (int e = 0; e < cE; e++){
            float wa = sm[OF_W1A + e*cH + k];
            float wb = sm[OF_W1B + e*cH + k];
            float2 h2 = hrow[e*4];
            a0  = fmaf(h2.x, wa, a0);  a1  = fmaf(h2.y, wa, a1);
            bv0 = fmaf(h2.x, wb, bv0); bv1 = fmaf(h2.y, wb, bv1);
        }
        #pragma unroll 8
        for (int c = 0; c < cH; c++){
            float wc = sm[OF_W1C + c*cH + k];
            float2 c2 = crow[c*4];
            bv0 = fmaf(c2.x, wc, bv0); bv1 = fmaf(c2.y, wc, bv1);
        }
        size_t i0 = (size_t)(bn0 + 2*g)*cH + k;
        g_A[i0]       = a0;
        g_A[i0 + cH]  = a1;
        g_Bv[i0]      = bv0;
        g_Bv[i0 + cH] = bv1;
    }
}

// ---------------- final edge MLP: 256 threads, 4 i per thread-half ----------------
__global__ void __launch_bounds__(256) final_kernel(const float* __restrict__ adj,
                                                    const float* __restrict__ gpre,
                                                    const float* __restrict__ W1,
                                                    const float* __restrict__ W2,
                                                    const float* __restrict__ b2,
                                                    float* __restrict__ out){
    extern __shared__ float sm[];
    float*  BvS = sm;                              // [j=128][k=128] pitch 129
    float*  A8  = sm + 128*129;                    // [8][128]
    float4* W3  = (float4*)(sm + 128*129 + 1024);
    int b = blockIdx.y, ic = blockIdx.x, tid = threadIdx.x;
    int j = tid & 127, half = tid >> 7;
    for (int r = half; r < cN; r += 2)
        BvS[r*129 + j] = g_Bv[((size_t)b*cN + r)*cH + j];
    #pragma unroll
    for (int ii = 0; ii < 4; ii++)
        A8[(half*4 + ii)*128 + j] = g_A[((size_t)b*cN + ic*8 + half*4 + ii)*cH + j];
    if (half == 0)
        W3[j] = make_float4(W1[(2*cE)*cH + j], W1[(2*cE + 1)*cH + j], W2[j], 0.f);
    float b2v = b2[0];
    __syncthreads();
    const float* brow = BvS + j*129;
    #pragma unroll
    for (int ii = 0; ii < 4; ii++){
        int i = ic*8 + half*4 + ii;
        size_t rbase = ((size_t)b*cN + i)*cN + j;
        float adjv = adj[rbase], gv = gpre[rbase];
        const float* arow = A8 + (half*4 + ii)*128;
        float acc = 0.f;
        #pragma unroll 4
        for (int k = 0; k < cH; k++){
            float4 ww = W3[k];
            float pre = arow[k] + brow[k] + adjv*ww.x + gv*ww.y;
            acc = fmaf(fmaxf(pre, 0.f), ww.z, acc);
        }
        out[rbase] = acc + b2v;
    }
}

// ---------------- launch ----------------
extern "C" void kernel_launch(void* const* d_in, const int* in_sizes, int n_in,
                              void* d_out, int out_size){
    const float* noisy_adj  = (const float*)d_in[0];
    const float* node_feats = (const float*)d_in[1];
    const float* feat_fnirs = (const float*)d_in[2];
    const float* feat_music = (const float*)d_in[3];
    const float* g_pre      = (const float*)d_in[4];
    const float* node_W     = (const float*)d_in[5];
    const float* node_b     = (const float*)d_in[6];
    const float* fnirs_W    = (const float*)d_in[7];
    const float* fnirs_b    = (const float*)d_in[8];
    const float* music_W    = (const float*)d_in[9];
    const float* music_b    = (const float*)d_in[10];
    const float* mlp_W1     = (const float*)d_in[11];
    const float* mlp_b1     = (const float*)d_in[12];
    const float* mlp_W2     = (const float*)d_in[13];
    const float* mlp_b2     = (const float*)d_in[14];
    const int*   t          = (const int*)d_in[15];

    float* out      = (float*)d_out;
    float* out_attn = out + cB*cN*cN;
    float* out_loss = out + cB*cN*cN + cB*cTf*cTm;

    cudaFuncSetAttribute(kv_kernel,    cudaFuncAttributeMaxDynamicSharedMemorySize, 139776);
    cudaFuncSetAttribute(attn_kernel,  cudaFuncAttributeMaxDynamicSharedMemorySize, ATTN_SMEM);
    cudaFuncSetAttribute(ab_kernel,    cudaFuncAttributeMaxDynamicSharedMemorySize, AB_SMEM);
    cudaFuncSetAttribute(final_kernel, cudaFuncAttributeMaxDynamicSharedMemorySize, 72192);

    cudaMemsetAsync(out_attn, 0, (size_t)(cB*cTf*cTm + 1)*sizeof(float));

    kv_kernel<<<dim3(8, cB), 256, 139776>>>(feat_music, music_W, music_b);
    qpre_kernel<<<cB*cN, 128>>>(feat_fnirs, fnirs_W, fnirs_b, t);
    attn_kernel<<<cB*16, 256, ATTN_SMEM>>>(t, out_attn, out_loss);
    ab_kernel<<<cB*16, 512, AB_SMEM>>>(node_feats, node_W, node_b, t, mlp_W1, mlp_b1);
    final_kernel<<<dim3(16, cB), 256, 72192>>>(noisy_adj, g_pre, mlp_W1, mlp_W2, mlp_b2, out);
}